// round 14
// baseline (speedup 1.0000x reference)
#include <cuda_runtime.h>
#include <cuda_fp16.h>
#include <math.h>
#include <stdint.h>

#define Bsz   4
#define Sseq  2048
#define Dm    768
#define Hh    16
#define DHh   48
#define NROWS (Bsz * Sseq)
#define XELEMS ((size_t)NROWS * Dm)
#define WELEMS ((size_t)Dm * Dm)

// softmax scale (1/sqrt(48)) * log2(e): folded into Q projection; exp2 in softmax
#define QSCALE 0.2082351f

// Scratch (__device__ globals per allocation-free rule)
__device__ float g_O[NROWS * Dm];
__device__ __half g_Wthi[3 * WELEMS];   // transposed W [n][k], fp16 hi
__device__ __half g_Wtlo[3 * WELEMS];   // fp16 residual
__device__ __half g_Qhi[XELEMS];        // Q needs hi only (A-side)
__device__ __half g_Khi[XELEMS];
__device__ __half g_Klo[XELEMS];
__device__ __half g_Vhi[XELEMS];
__device__ __half g_Vlo[XELEMS];

// ============================ PTX helpers ==================================
__device__ __forceinline__ uint32_t smem_u32(const void* p) {
    uint32_t a;
    asm("{ .reg .u64 t; cvta.to.shared.u64 t, %1; cvt.u32.u64 %0, t; }" : "=r"(a) : "l"(p));
    return a;
}
__device__ __forceinline__ float ex2(float x) {
    float y; asm("ex2.approx.ftz.f32 %0, %1;" : "=f"(y) : "f"(x)); return y;
}
#define MMA16816(C, a0, a1, a2, a3, b0, b1)                                   \
    asm volatile("mma.sync.aligned.m16n8k16.row.col.f32.f16.f16.f32 "         \
        "{%0,%1,%2,%3}, {%4,%5,%6,%7}, {%8,%9}, {%0,%1,%2,%3};"               \
        : "+f"((C)[0]), "+f"((C)[1]), "+f"((C)[2]), "+f"((C)[3])              \
        : "r"(a0), "r"(a1), "r"(a2), "r"(a3), "r"(b0), "r"(b1))
#define LDSM_X4(r0, r1, r2, r3, addr)                                         \
    asm volatile("ldmatrix.sync.aligned.m8n8.x4.shared.b16 {%0,%1,%2,%3}, [%4];" \
        : "=r"(r0), "=r"(r1), "=r"(r2), "=r"(r3) : "r"(addr))
#define LDSM_X4T(r0, r1, r2, r3, addr)                                        \
    asm volatile("ldmatrix.sync.aligned.m8n8.x4.trans.shared.b16 {%0,%1,%2,%3}, [%4];" \
        : "=r"(r0), "=r"(r1), "=r"(r2), "=r"(r3) : "r"(addr))
#define CP_ASYNC16(sa, ga)                                                    \
    asm volatile("cp.async.cg.shared.global [%0], [%1], 16;" :: "r"(sa), "l"(ga))
#define CP_COMMIT() asm volatile("cp.async.commit_group;" ::: "memory")
#define CP_WAIT1()  asm volatile("cp.async.wait_group 1;" ::: "memory")
#define CP_WAIT0()  asm volatile("cp.async.wait_group 0;" ::: "memory")

// Pack two floats to fp16x2 (x -> low half, y -> high half)
__device__ __forceinline__ uint32_t pack_h2(float x, float y) {
    uint32_t r;
    asm("cvt.rn.f16x2.f32 %0, %1, %2;" : "=r"(r) : "f"(y), "f"(x));
    return r;
}
// fp16 split: hi = RN(x), lo = RN(x - hi)
__device__ __forceinline__ uint32_t split_h2(float x, float y, uint32_t& lo) {
    uint32_t hi = pack_h2(x, y);
    __half2 h2 = *(__half2*)&hi;
    float xl = x - __low2float(h2);
    float yl = y - __high2float(h2);
    lo = pack_h2(xl, yl);
    return hi;
}

// ============================ W converter ==================================
__global__ __launch_bounds__(256) void convert_w_kernel(
    const float* __restrict__ wq, const float* __restrict__ wk,
    const float* __restrict__ wv,
    __half* __restrict__ hi, __half* __restrict__ lo)
{
    __shared__ float tile[32][33];
    int z = blockIdx.z;
    const float* W = (z == 0) ? wq : (z == 1) ? wk : wv;
    size_t base = (size_t)z * WELEMS;
    int tx = threadIdx.x, ty = threadIdx.y;
    int bx = blockIdx.x, by = blockIdx.y;
#pragma unroll
    for (int i = 0; i < 4; i++) {
        int kk = by * 32 + ty + i * 8;
        int n = bx * 32 + tx;
        tile[ty + i * 8][tx] = W[kk * Dm + n];
    }
    __syncthreads();
#pragma unroll
    for (int i = 0; i < 4; i++) {
        int n = bx * 32 + ty + i * 8;
        int kk = by * 32 + tx;
        float v = tile[tx][ty + i * 8];
        __half h = __float2half_rn(v);
        __half l = __float2half_rn(v - __half2float(h));
        hi[base + n * Dm + kk] = h;
        lo[base + n * Dm + kk] = l;
    }
}

// ================= batched mma.sync GEMM (fp16 split-2) ====================
// Y = (X@W + bias)*scale. A = fp16(X) in-kernel (hi only); B = Whi + Wlo.
// D = Ah*Bh + Ah*Bl. CTA 128x128, BK=96, 512 threads, warp tile 32x32.
#define GBK   96
#define GLDA  104                             // 96 + 8 pad (208 B rows)
#define GPART (128 * GLDA * 2)                // 26624 B per operand array
#define GBUF  (3 * GPART)                     // Ah, Bh, Bl = 79872 B
#define GEMM_SMEM_BYTES (2 * GBUF)            // 159744 B
#define GNCHK (Dm / GBK)                      // 8

__global__ __launch_bounds__(512) void gemm_mma_kernel(
    const float* __restrict__ xq, const float* __restrict__ xk,
    const float* __restrict__ xv,
    const __half* __restrict__ whi, const __half* __restrict__ wlo,
    const float* __restrict__ bq, const float* __restrict__ bk,
    const float* __restrict__ bv,
    __half* __restrict__ qhi,
    __half* __restrict__ khi, __half* __restrict__ klo,
    __half* __restrict__ vhi, __half* __restrict__ vlo)
{
    extern __shared__ __align__(128) char smraw[];
    uint32_t smb = smem_u32(smraw);
    int z = blockIdx.z;
    const float* Af = (z == 0) ? xq : (z == 1) ? xk : xv;
    const __half* Bhi = whi + (size_t)z * WELEMS;
    const __half* Blo = wlo + (size_t)z * WELEMS;
    const float* bias = (z == 0) ? bq : (z == 1) ? bk : bv;
    __half* Yhi = (z == 0) ? qhi : (z == 1) ? khi : vhi;
    __half* Ylo = (z == 0) ? (__half*)0 : (z == 1) ? klo : vlo;
    float scale = (z == 0) ? QSCALE : 1.0f;

    int tid = threadIdx.x;
    int w = tid >> 5, lane = tid & 31;
    int bm = blockIdx.y * 128;
    int bn = blockIdx.x * 128;

    int wm = (w >> 2) * 32;
    int wn = (w & 3) * 32;

    int mat = lane >> 3;
    int arow = ((mat & 1) << 3) + (lane & 7);
    int acol8 = (mat >> 1) << 3;
    int brow = ((mat >> 1) << 3) + (lane & 7);
    int bcol8 = (mat & 1) << 3;

    float c[2][4][4];
#pragma unroll
    for (int mf = 0; mf < 2; mf++)
#pragma unroll
        for (int nf = 0; nf < 4; nf++)
#pragma unroll
            for (int e = 0; e < 4; e++) c[mf][nf][e] = 0.f;

// B: 2 arrays x 128 rows x 12 segs(16B) = 3072 -> 6/thread
#define B_ISSUE(c0, bufsel) do {                                              \
    int k0_ = (c0) * GBK;                                                     \
    uint32_t bb_ = smb + (bufsel) * GBUF;                                     \
    _Pragma("unroll")                                                         \
    for (int it = 0; it < 6; it++) {                                          \
        int idx = tid + it * 512;                                             \
        int part = idx / 1536;                                                \
        int rem = idx - part * 1536;                                          \
        int row = rem / 12, seg = rem - row * 12;                             \
        const __half* ga = (part ? Blo : Bhi) +                               \
            (size_t)(bn + row) * Dm + k0_ + seg * 8;                          \
        uint32_t sa = bb_ + (1 + part) * GPART + row * (GLDA * 2) + seg * 16; \
        CP_ASYNC16(sa, ga);                                                   \
    }                                                                         \
    CP_COMMIT();                                                              \
} while (0)

// A: 128 rows x 24 float4/row = 3072 -> 6/thread
#define A_LDG(c0, regs) do {                                                  \
    int k0_ = (c0) * GBK;                                                     \
    _Pragma("unroll")                                                         \
    for (int it = 0; it < 6; it++) {                                          \
        int idx = tid + it * 512;                                             \
        int row = idx / 24, cseg = idx - row * 24;                            \
        (regs)[it] = *(const float4*)(Af +                                    \
            (size_t)(bm + row) * Dm + k0_ + cseg * 4);                        \
    }                                                                         \
} while (0)

#define A_STS(bufsel, regs) do {                                              \
    _Pragma("unroll")                                                         \
    for (int it = 0; it < 6; it++) {                                          \
        int idx = tid + it * 512;                                             \
        int row = idx / 24, cseg = idx - row * 24;                            \
        float4 v = (regs)[it];                                                \
        uint32_t h01 = pack_h2(v.x, v.y);                                     \
        uint32_t h23 = pack_h2(v.z, v.w);                                     \
        uint32_t off = row * (GLDA * 2) + cseg * 8;                           \
        *(uint2*)(smraw + (bufsel) * GBUF + off) = make_uint2(h01, h23);      \
    }                                                                         \
} while (0)

    float4 aregs[6];
    B_ISSUE(0, 0);
    A_LDG(0, aregs);
    A_STS(0, aregs);

    for (int cc = 0; cc < GNCHK; cc++) {
        int buf = cc & 1;
        if (cc + 1 < GNCHK) {
            A_LDG(cc + 1, aregs);
            B_ISSUE(cc + 1, buf ^ 1);
            CP_WAIT1();
        } else {
            CP_WAIT0();
        }
        __syncthreads();

        uint32_t bb = smb + buf * GBUF;
        uint32_t sAh = bb, sBh = bb + GPART, sBl = bb + 2 * GPART;

#pragma unroll
        for (int ks = 0; ks < 6; ks++) {
            uint32_t ah[2][4];
#pragma unroll
            for (int mf = 0; mf < 2; mf++) {
                uint32_t a = ((wm + mf * 16 + arow) * GLDA + ks * 16 + acol8) * 2;
                LDSM_X4(ah[mf][0], ah[mf][1], ah[mf][2], ah[mf][3], sAh + a);
            }
            uint32_t bh[4][2], bl[4][2];
#pragma unroll
            for (int nf2 = 0; nf2 < 2; nf2++) {
                uint32_t a = ((wn + nf2 * 16 + brow) * GLDA + ks * 16 + bcol8) * 2;
                uint32_t r0, r1, r2, r3;
                LDSM_X4(r0, r1, r2, r3, sBh + a);
                bh[nf2 * 2][0] = r0; bh[nf2 * 2][1] = r1;
                bh[nf2 * 2 + 1][0] = r2; bh[nf2 * 2 + 1][1] = r3;
                LDSM_X4(r0, r1, r2, r3, sBl + a);
                bl[nf2 * 2][0] = r0; bl[nf2 * 2][1] = r1;
                bl[nf2 * 2 + 1][0] = r2; bl[nf2 * 2 + 1][1] = r3;
            }
#pragma unroll
            for (int mf = 0; mf < 2; mf++)
#pragma unroll
                for (int nf = 0; nf < 4; nf++) {
                    MMA16816(c[mf][nf], ah[mf][0], ah[mf][1], ah[mf][2], ah[mf][3],
                             bh[nf][0], bh[nf][1]);
                    MMA16816(c[mf][nf], ah[mf][0], ah[mf][1], ah[mf][2], ah[mf][3],
                             bl[nf][0], bl[nf][1]);
                }
        }

        if (cc + 1 < GNCHK) A_STS(buf ^ 1, aregs);
        __syncthreads();
    }

    // Epilogue: stage f32 tile, bias+scale, emit fp16 (hi, and lo for K/V)
    float* sOut = (float*)smraw;
    int g = lane >> 2, t4 = lane & 3;
#pragma unroll
    for (int mf = 0; mf < 2; mf++) {
        int m0 = wm + mf * 16 + g;
#pragma unroll
        for (int nf = 0; nf < 4; nf++) {
            int col = wn + nf * 8 + t4 * 2;
            sOut[m0 * 128 + col]       = c[mf][nf][0];
            sOut[m0 * 128 + col + 1]   = c[mf][nf][1];
            sOut[(m0 + 8) * 128 + col]     = c[mf][nf][2];
            sOut[(m0 + 8) * 128 + col + 1] = c[mf][nf][3];
        }
    }
    __syncthreads();

    bool write_lo = (Ylo != (__half*)0);
#pragma unroll
    for (int it = 0; it < 8; it++) {
        int idx = tid + it * 512;
        int row = idx >> 5, c4 = (idx & 31) * 4;
        float4 o = *(float4*)(sOut + row * 128 + c4);
        const float* bp = bias + bn + c4;
        float y0 = (o.x + bp[0]) * scale;
        float y1 = (o.y + bp[1]) * scale;
        float y2 = (o.z + bp[2]) * scale;
        float y3 = (o.w + bp[3]) * scale;
        size_t off = (size_t)(bm + row) * Dm + bn + c4;
        if (write_lo) {
            uint32_t l01, l23;
            uint32_t h01 = split_h2(y0, y1, l01);
            uint32_t h23 = split_h2(y2, y3, l23);
            *(uint2*)(Yhi + off) = make_uint2(h01, h23);
            *(uint2*)(Ylo + off) = make_uint2(l01, l23);
        } else {
            uint32_t h01 = pack_h2(y0, y1);
            uint32_t h23 = pack_h2(y2, y3);
            *(uint2*)(Yhi + off) = make_uint2(h01, h23);
        }
    }
}

// ============ register-resident flash attention (fp16 split-2) =============
// S = Qh*Kh + Qh*Kl ;  O += Ph*Vh + Ph*Vl.  V loads via ldmatrix.x4.trans.
#define LDA 56
#define QARR (128 * LDA * 2)
#define KARR (64 * LDA * 2)
#define BUFB (4 * KARR)
#define ATTN_SMEM (QARR + 3 * BUFB)

__global__ __launch_bounds__(256, 2) void attn_reg_kernel(
    const __half* __restrict__ Qh_g,
    const __half* __restrict__ Kh_g, const __half* __restrict__ Kl_g,
    const __half* __restrict__ Vh_g, const __half* __restrict__ Vl_g,
    float* __restrict__ Og)
{
    extern __shared__ __align__(128) char smraw[];
    uint32_t smb = smem_u32(smraw);
    __half* Qh = (__half*)smraw;

    int qt = (int)gridDim.x - 1 - (int)blockIdx.x;
    int bh = blockIdx.y;
    int b = bh >> 4, h = bh & 15;
    int tid = threadIdx.x;
    int w = tid >> 5, lane = tid & 31;
    int rowbase = b * Sseq;
    int q0 = qt * 128;
    int hoff = h * DHh;
    int ntiles = 2 * qt + 2;

    {
#pragma unroll
        for (int it = 0; it < 6; it++) {
            int s = tid + it * 256;
            int arr = s / 384, rem = s - arr * 384;
            int r = rem / 6, c16 = rem - r * 6;
            const __half* src = (arr == 0) ? Kh_g : (arr == 1) ? Kl_g :
                                (arr == 2) ? Vh_g : Vl_g;
            const __half* ga = src + (size_t)(rowbase + r) * Dm + hoff + c16 * 8;
            uint32_t sa = smb + QARR + arr * KARR + r * (LDA * 2) + c16 * 16;
            CP_ASYNC16(sa, ga);
        }
        CP_COMMIT();
    }

    for (int s = tid; s < 768; s += 256) {
        int r = s / 6, c8 = (s % 6) * 8;
        *(uint4*)(Qh + r * LDA + c8) =
            *(const uint4*)(Qh_g + (size_t)(rowbase + q0 + r) * Dm + hoff + c8);
    }
    __syncthreads();

    int mat = lane >> 3;
    int qrow_loc = ((mat & 1) << 3) + (lane & 7);   // also V x4.trans row map
    int qcol8 = (mat >> 1) << 3;                    // also V x4.trans col-block
    int brow = ((mat >> 1) << 3) + (lane & 7);
    int bcol8 = (mat & 1) << 3;

    uint32_t qh[3][4];
#pragma unroll
    for (int ks = 0; ks < 3; ks++) {
        uint32_t a = smb + ((w * 16 + qrow_loc) * LDA + ks * 16 + qcol8) * 2;
        LDSM_X4(qh[ks][0], qh[ks][1], qh[ks][2], qh[ks][3], a);
    }

    int g = lane >> 2, t4 = lane & 3;

    float m0 = -1e30f, m1 = -1e30f, l0 = 0.f, l1 = 0.f;
    float o[6][4];
#pragma unroll
    for (int on = 0; on < 6; on++)
#pragma unroll
        for (int e = 0; e < 4; e++) o[on][e] = 0.f;

    for (int j = 0; j < ntiles; j++) {
        if (j + 1 < ntiles) {
            int k0n = (j + 1) * 64;
            uint32_t bb = smb + QARR + ((j + 1) % 3) * BUFB;
#pragma unroll
            for (int it = 0; it < 6; it++) {
                int s = tid + it * 256;
                int arr = s / 384, rem = s - arr * 384;
                int r = rem / 6, c16 = rem - r * 6;
                const __half* src = (arr == 0) ? Kh_g : (arr == 1) ? Kl_g :
                                    (arr == 2) ? Vh_g : Vl_g;
                const __half* ga = src + (size_t)(rowbase + k0n + r) * Dm + hoff + c16 * 8;
                uint32_t sa = bb + arr * KARR + r * (LDA * 2) + c16 * 16;
                CP_ASYNC16(sa, ga);
            }
            CP_COMMIT();
            CP_WAIT1();
        } else {
            CP_WAIT0();
        }
        __syncthreads();

        uint32_t bufb = smb + QARR + (j % 3) * BUFB;
        uint32_t bufKh = bufb, bufKl = bufb + KARR;
        uint32_t bufVh = bufb + 2 * KARR, bufVl = bufb + 3 * KARR;

        // ---- S = Qh Kh^T + Qh Kl^T ----
        float sc[8][4];
#pragma unroll
        for (int jn2 = 0; jn2 < 4; jn2++) {
#pragma unroll
            for (int e = 0; e < 4; e++) { sc[2*jn2][e] = 0.f; sc[2*jn2+1][e] = 0.f; }
#pragma unroll
            for (int ks = 0; ks < 3; ks++) {
                uint32_t a = ((jn2 * 16 + brow) * LDA + ks * 16 + bcol8) * 2;
                uint32_t kh0, kh1, kh2, kh3, kl0, kl1, kl2, kl3;
                LDSM_X4(kh0, kh1, kh2, kh3, bufKh + a);
                LDSM_X4(kl0, kl1, kl2, kl3, bufKl + a);
                MMA16816(sc[2*jn2],   qh[ks][0], qh[ks][1], qh[ks][2], qh[ks][3], kh0, kh1);
                MMA16816(sc[2*jn2],   qh[ks][0], qh[ks][1], qh[ks][2], qh[ks][3], kl0, kl1);
                MMA16816(sc[2*jn2+1], qh[ks][0], qh[ks][1], qh[ks][2], qh[ks][3], kh2, kh3);
                MMA16816(sc[2*jn2+1], qh[ks][0], qh[ks][1], qh[ks][2], qh[ks][3], kl2, kl3);
            }
        }

        int k0 = j * 64;
        if (j >= 2 * qt) {
            int qg0 = q0 + w * 16 + g;
#pragma unroll
            for (int jn = 0; jn < 8; jn++) {
                int cix = k0 + jn * 8 + 2 * t4;
                if (qg0 < cix)     sc[jn][0] = -1e30f;
                if (qg0 < cix + 1) sc[jn][1] = -1e30f;
                if (qg0 + 8 < cix)     sc[jn][2] = -1e30f;
                if (qg0 + 8 < cix + 1) sc[jn][3] = -1e30f;
            }
        }

        float mx0 = -1e30f, mx1 = -1e30f;
#pragma unroll
        for (int jn = 0; jn < 8; jn++) {
            mx0 = fmaxf(mx0, fmaxf(sc[jn][0], sc[jn][1]));
            mx1 = fmaxf(mx1, fmaxf(sc[jn][2], sc[jn][3]));
        }
        mx0 = fmaxf(mx0, __shfl_xor_sync(0xffffffffu, mx0, 1));
        mx0 = fmaxf(mx0, __shfl_xor_sync(0xffffffffu, mx0, 2));
        mx1 = fmaxf(mx1, __shfl_xor_sync(0xffffffffu, mx1, 1));
        mx1 = fmaxf(mx1, __shfl_xor_sync(0xffffffffu, mx1, 2));
        float mn0 = fmaxf(m0, mx0), mn1 = fmaxf(m1, mx1);
        float al0 = ex2(m0 - mn0), al1 = ex2(m1 - mn1);
        m0 = mn0; m1 = mn1;
        float ps0 = 0.f, ps1 = 0.f;
#pragma unroll
        for (int jn = 0; jn < 8; jn++) {
            sc[jn][0] = ex2(sc[jn][0] - mn0);
            sc[jn][1] = ex2(sc[jn][1] - mn0);
            sc[jn][2] = ex2(sc[jn][2] - mn1);
            sc[jn][3] = ex2(sc[jn][3] - mn1);
            ps0 += sc[jn][0] + sc[jn][1];
            ps1 += sc[jn][2] + sc[jn][3];
        }
        ps0 += __shfl_xor_sync(0xffffffffu, ps0, 1);
        ps0 += __shfl_xor_sync(0xffffffffu, ps0, 2);
        ps1 += __shfl_xor_sync(0xffffffffu, ps1, 1);
        ps1 += __shfl_xor_sync(0xffffffffu, ps1, 2);
        l0 = l0 * al0 + ps0;
        l1 = l1 * al1 + ps1;

#pragma unroll
        for (int on = 0; on < 6; on++) {
            o[on][0] *= al0; o[on][1] *= al0;
            o[on][2] *= al1; o[on][3] *= al1;
        }
        // ---- O += P Vh + P Vl : V via x4.trans (2 n8-tiles per load) ----
#pragma unroll
        for (int ks = 0; ks < 4; ks++) {
            uint32_t pa[4];
            pa[0] = pack_h2(sc[2*ks][0],   sc[2*ks][1]);
            pa[1] = pack_h2(sc[2*ks][2],   sc[2*ks][3]);
            pa[2] = pack_h2(sc[2*ks+1][0], sc[2*ks+1][1]);
            pa[3] = pack_h2(sc[2*ks+1][2], sc[2*ks+1][3]);
#pragma unroll
            for (int on2 = 0; on2 < 3; on2++) {
                uint32_t va = ((ks * 16 + qrow_loc) * LDA + on2 * 16 + qcol8) * 2;
                uint32_t vh0, vh1, vh2, vh3, vl0, vl1, vl2, vl3;
                LDSM_X4T(vh0, vh1, vh2, vh3, bufVh + va);
                LDSM_X4T(vl0, vl1, vl2, vl3, bufVl + va);
                MMA16816(o[2*on2],   pa[0], pa[1], pa[2], pa[3], vh0, vh1);
                MMA16816(o[2*on2],   pa[0], pa[1], pa[2], pa[3], vl0, vl1);
                MMA16816(o[2*on2+1], pa[0], pa[1], pa[2], pa[3], vh2, vh3);
                MMA16816(o[2*on2+1], pa[0], pa[1], pa[2], pa[3], vl2, vl3);
            }
        }
        __syncthreads();
    }

    float inv0 = 1.f / l0, inv1 = 1.f / l1;
    float* op0 = Og + (size_t)(rowbase + q0 + w * 16 + g) * Dm + hoff + 2 * t4;
    float* op1 = op0 + 8 * Dm;
#pragma unroll
    for (int on = 0; on < 6; on++) {
        float2 r0 = make_float2(o[on][0] * inv0, o[on][1] * inv0);
        float2 r1 = make_float2(o[on][2] * inv1, o[on][3] * inv1);
        *(float2*)(op0 + on * 8) = r0;
        *(float2*)(op1 + on * 8) = r1;
    }
}

// ---------------------------------------------------------------------------
// LayerNorm: 192 threads/row, float4 per thread.
// ---------------------------------------------------------------------------
__global__ __launch_bounds__(192) void ln_kernel(
    const float* __restrict__ X, const float* __restrict__ gamma,
    const float* __restrict__ beta, float* __restrict__ Y)
{
    int row = blockIdx.x;
    int tid = threadIdx.x;
    const float* x = X + (size_t)row * Dm;

    float4 v = *(const float4*)(x + tid * 4);
    float s  = v.x + v.y + v.z + v.w;
    float sq = v.x * v.x + v.y * v.y + v.z * v.z + v.w * v.w;

#pragma unroll
    for (int off = 16; off > 0; off >>= 1) {
        s  += __shfl_xor_sync(0xffffffffu, s, off);
        sq += __shfl_xor_sync(0xffffffffu, sq, off);
    }
    __shared__ float red_s[6], red_q[6];
    int wid = tid >> 5, lid = tid & 31;
    if (lid == 0) { red_s[wid] = s; red_q[wid] = sq; }
    __syncthreads();
    float ts = 0.f, tq = 0.f;
#pragma unroll
    for (int i = 0; i < 6; i++) { ts += red_s[i]; tq += red_q[i]; }
    float mu  = ts * (1.f / Dm);
    float var = tq * (1.f / Dm) - mu * mu;
    float inv = rsqrtf(var + 1e-3f);

    float4 gmv = *(const float4*)(gamma + tid * 4);
    float4 btv = *(const float4*)(beta + tid * 4);
    float4 yv;
    yv.x = (v.x - mu) * inv * gmv.x + btv.x;
    yv.y = (v.y - mu) * inv * gmv.y + btv.y;
    yv.z = (v.z - mu) * inv * gmv.z + btv.z;
    yv.w = (v.w - mu) * inv * gmv.w + btv.w;
    *(float4*)(Y + (size_t)row * Dm + tid * 4) = yv;
}

// ---------------------------------------------------------------------------
extern "C" void kernel_launch(void* const* d_in, const int* in_sizes, int n_in,
                              void* d_out, int out_size)
{
    const float* q     = (const float*)d_in[0];
    const float* k     = (const float*)d_in[1];
    const float* v     = (const float*)d_in[2];
    const float* Wq    = (const float*)d_in[3];
    const float* bq    = (const float*)d_in[4];
    const float* Wk    = (const float*)d_in[5];
    const float* bk    = (const float*)d_in[6];
    const float* Wv    = (const float*)d_in[7];
    const float* bv    = (const float*)d_in[8];
    const float* gamma = (const float*)d_in[9];
    const float* beta  = (const float*)d_in[10];
    float* out = (float*)d_out;

    float* Og;
    __half *whi, *wlo, *qhi, *khi, *klo, *vhi, *vlo;
    cudaGetSymbolAddress((void**)&Og, g_O);
    cudaGetSymbolAddress((void**)&whi, g_Wthi);
    cudaGetSymbolAddress((void**)&wlo, g_Wtlo);
    cudaGetSymbolAddress((void**)&qhi, g_Qhi);
    cudaGetSymbolAddress((void**)&khi, g_Khi);
    cudaGetSymbolAddress((void**)&klo, g_Klo);
    cudaGetSymbolAddress((void**)&vhi, g_Vhi);
    cudaGetSymbolAddress((void**)&vlo, g_Vlo);

    cudaFuncSetAttribute(gemm_mma_kernel, cudaFuncAttributeMaxDynamicSharedMemorySize,
                         GEMM_SMEM_BYTES);
    cudaFuncSetAttribute(attn_reg_kernel, cudaFuncAttributeMaxDynamicSharedMemorySize,
                         ATTN_SMEM);

    convert_w_kernel<<<dim3(Dm / 32, Dm / 32, 3), dim3(32, 8)>>>(Wq, Wk, Wv, whi, wlo);

    gemm_mma_kernel<<<dim3(Dm / 128, NROWS / 128, 3), 512, GEMM_SMEM_BYTES>>>(
        q, k, v, whi, wlo, bq, bk, bv, qhi, khi, klo, vhi, vlo);

    attn_reg_kernel<<<dim3(Sseq / 128, Bsz * Hh), 256, ATTN_SMEM>>>(
        qhi, khi, klo, vhi, vlo, Og);

    ln_kernel<<<NROWS, 192>>>(Og, gamma, beta, out);
}

// round 15
// speedup vs baseline: 1.0262x; 1.0262x over previous
#include <cuda_runtime.h>
#include <cuda_fp16.h>
#include <math.h>
#include <stdint.h>

#define Bsz   4
#define Sseq  2048
#define Dm    768
#define Hh    16
#define DHh   48
#define NROWS (Bsz * Sseq)
#define XELEMS ((size_t)NROWS * Dm)
#define WELEMS ((size_t)Dm * Dm)

// softmax scale (1/sqrt(48)) * log2(e): folded into Q projection; exp2 in softmax
#define QSCALE 0.2082351f

// Scratch (__device__ globals per allocation-free rule)
__device__ float g_O[NROWS * Dm];
__device__ __half g_Wthi[3 * WELEMS];   // transposed W [n][k], fp16 hi
__device__ __half g_Wtlo[3 * WELEMS];   // fp16 residual
__device__ __half g_Qhi[XELEMS];        // Q needs hi only (A-side)
__device__ __half g_Khi[XELEMS];
__device__ __half g_Klo[XELEMS];
__device__ __half g_Vhi[XELEMS];
__device__ __half g_Vlo[XELEMS];

// ============================ PTX helpers ==================================
__device__ __forceinline__ uint32_t smem_u32(const void* p) {
    uint32_t a;
    asm("{ .reg .u64 t; cvta.to.shared.u64 t, %1; cvt.u32.u64 %0, t; }" : "=r"(a) : "l"(p));
    return a;
}
__device__ __forceinline__ float ex2(float x) {
    float y; asm("ex2.approx.ftz.f32 %0, %1;" : "=f"(y) : "f"(x)); return y;
}
#define MMA16816(C, a0, a1, a2, a3, b0, b1)                                   \
    asm volatile("mma.sync.aligned.m16n8k16.row.col.f32.f16.f16.f32 "         \
        "{%0,%1,%2,%3}, {%4,%5,%6,%7}, {%8,%9}, {%0,%1,%2,%3};"               \
        : "+f"((C)[0]), "+f"((C)[1]), "+f"((C)[2]), "+f"((C)[3])              \
        : "r"(a0), "r"(a1), "r"(a2), "r"(a3), "r"(b0), "r"(b1))
#define LDSM_X4(r0, r1, r2, r3, addr)                                         \
    asm volatile("ldmatrix.sync.aligned.m8n8.x4.shared.b16 {%0,%1,%2,%3}, [%4];" \
        : "=r"(r0), "=r"(r1), "=r"(r2), "=r"(r3) : "r"(addr))
#define LDSM_X4T(r0, r1, r2, r3, addr)                                        \
    asm volatile("ldmatrix.sync.aligned.m8n8.x4.trans.shared.b16 {%0,%1,%2,%3}, [%4];" \
        : "=r"(r0), "=r"(r1), "=r"(r2), "=r"(r3) : "r"(addr))
#define CP_ASYNC16(sa, ga)                                                    \
    asm volatile("cp.async.cg.shared.global [%0], [%1], 16;" :: "r"(sa), "l"(ga))
#define CP_COMMIT() asm volatile("cp.async.commit_group;" ::: "memory")
#define CP_WAIT1()  asm volatile("cp.async.wait_group 1;" ::: "memory")
#define CP_WAIT0()  asm volatile("cp.async.wait_group 0;" ::: "memory")

// Pack two floats to fp16x2 (x -> low half, y -> high half)
__device__ __forceinline__ uint32_t pack_h2(float x, float y) {
    uint32_t r;
    asm("cvt.rn.f16x2.f32 %0, %1, %2;" : "=r"(r) : "f"(y), "f"(x));
    return r;
}
// fp16 split: hi = RN(x), lo = RN(x - hi)
__device__ __forceinline__ uint32_t split_h2(float x, float y, uint32_t& lo) {
    uint32_t hi = pack_h2(x, y);
    __half2 h2 = *(__half2*)&hi;
    float xl = x - __low2float(h2);
    float yl = y - __high2float(h2);
    lo = pack_h2(xl, yl);
    return hi;
}

// ============================ W converter ==================================
__global__ __launch_bounds__(256) void convert_w_kernel(
    const float* __restrict__ wq, const float* __restrict__ wk,
    const float* __restrict__ wv,
    __half* __restrict__ hi, __half* __restrict__ lo)
{
    __shared__ float tile[32][33];
    int z = blockIdx.z;
    const float* W = (z == 0) ? wq : (z == 1) ? wk : wv;
    size_t base = (size_t)z * WELEMS;
    int tx = threadIdx.x, ty = threadIdx.y;
    int bx = blockIdx.x, by = blockIdx.y;
#pragma unroll
    for (int i = 0; i < 4; i++) {
        int kk = by * 32 + ty + i * 8;
        int n = bx * 32 + tx;
        tile[ty + i * 8][tx] = W[kk * Dm + n];
    }
    __syncthreads();
#pragma unroll
    for (int i = 0; i < 4; i++) {
        int n = bx * 32 + ty + i * 8;
        int kk = by * 32 + tx;
        float v = tile[tx][ty + i * 8];
        __half h = __float2half_rn(v);
        __half l = __float2half_rn(v - __half2float(h));
        hi[base + n * Dm + kk] = h;
        lo[base + n * Dm + kk] = l;
    }
}

// ================= batched mma.sync GEMM (fp16 split-2) ====================
// Y = (X@W + bias)*scale. A = fp16(X) in-kernel (hi only); B = Whi + Wlo.
// D = Ah*Bh + Ah*Bl. CTA 128x128, BK=64, 512 threads, warp tile 32x32.
#define GBK   64
#define GLDA  72                              // 64 + 8 pad (144 B rows)
#define GPART (128 * GLDA * 2)                // 18432 B per operand array
#define GBUF  (3 * GPART)                     // Ah, Bh, Bl = 55296 B
#define GEMM_SMEM_BYTES (2 * GBUF)            // 110592 B (epilogue 64 KB fits)
#define GNCHK (Dm / GBK)                      // 12

__global__ __launch_bounds__(512) void gemm_mma_kernel(
    const float* __restrict__ xq, const float* __restrict__ xk,
    const float* __restrict__ xv,
    const __half* __restrict__ whi, const __half* __restrict__ wlo,
    const float* __restrict__ bq, const float* __restrict__ bk,
    const float* __restrict__ bv,
    __half* __restrict__ qhi,
    __half* __restrict__ khi, __half* __restrict__ klo,
    __half* __restrict__ vhi, __half* __restrict__ vlo)
{
    extern __shared__ __align__(128) char smraw[];
    uint32_t smb = smem_u32(smraw);
    int z = blockIdx.z;
    const float* Af = (z == 0) ? xq : (z == 1) ? xk : xv;
    const __half* Bhi = whi + (size_t)z * WELEMS;
    const __half* Blo = wlo + (size_t)z * WELEMS;
    const float* bias = (z == 0) ? bq : (z == 1) ? bk : bv;
    __half* Yhi = (z == 0) ? qhi : (z == 1) ? khi : vhi;
    __half* Ylo = (z == 0) ? (__half*)0 : (z == 1) ? klo : vlo;
    float scale = (z == 0) ? QSCALE : 1.0f;

    int tid = threadIdx.x;
    int w = tid >> 5, lane = tid & 31;
    int bm = blockIdx.y * 128;
    int bn = blockIdx.x * 128;

    int wm = (w >> 2) * 32;
    int wn = (w & 3) * 32;

    int mat = lane >> 3;
    int arow = ((mat & 1) << 3) + (lane & 7);
    int acol8 = (mat >> 1) << 3;
    int brow = ((mat >> 1) << 3) + (lane & 7);
    int bcol8 = (mat & 1) << 3;

    // A loader: 128 rows x 16 float4/row = 2048 -> 4/thread
    int a_row0 = tid >> 4, a_f4 = (tid & 15);

    float c[2][4][4];
#pragma unroll
    for (int mf = 0; mf < 2; mf++)
#pragma unroll
        for (int nf = 0; nf < 4; nf++)
#pragma unroll
            for (int e = 0; e < 4; e++) c[mf][nf][e] = 0.f;

// B: 2 arrays x 128 rows x 8 segs(16B) = 2048 -> 4/thread
#define B_ISSUE(c0, bufsel) do {                                              \
    int k0_ = (c0) * GBK;                                                     \
    uint32_t bb_ = smb + (bufsel) * GBUF;                                     \
    _Pragma("unroll")                                                         \
    for (int it = 0; it < 4; it++) {                                          \
        int idx = tid + it * 512;                                             \
        int part = idx >> 10;                                                 \
        int rem = idx & 1023;                                                 \
        int row = rem >> 3, seg = rem & 7;                                    \
        const __half* ga = (part ? Blo : Bhi) +                               \
            (size_t)(bn + row) * Dm + k0_ + seg * 8;                          \
        uint32_t sa = bb_ + (1 + part) * GPART + row * (GLDA * 2) + seg * 16; \
        CP_ASYNC16(sa, ga);                                                   \
    }                                                                         \
    CP_COMMIT();                                                              \
} while (0)

#define A_LDG(c0, regs) do {                                                  \
    int k0_ = (c0) * GBK;                                                     \
    _Pragma("unroll")                                                         \
    for (int it = 0; it < 4; it++)                                            \
        (regs)[it] = *(const float4*)(Af +                                    \
            (size_t)(bm + a_row0 + it * 32) * Dm + k0_ + a_f4 * 4);           \
} while (0)

#define A_STS(bufsel, regs) do {                                              \
    _Pragma("unroll")                                                         \
    for (int it = 0; it < 4; it++) {                                          \
        int row = a_row0 + it * 32;                                           \
        float4 v = (regs)[it];                                                \
        uint32_t h01 = pack_h2(v.x, v.y);                                     \
        uint32_t h23 = pack_h2(v.z, v.w);                                     \
        uint32_t off = row * (GLDA * 2) + a_f4 * 8;                           \
        *(uint2*)(smraw + (bufsel) * GBUF + off) = make_uint2(h01, h23);      \
    }                                                                         \
} while (0)

    float4 aregs[4];
    B_ISSUE(0, 0);
    A_LDG(0, aregs);
    A_STS(0, aregs);

    for (int cc = 0; cc < GNCHK; cc++) {
        int buf = cc & 1;
        if (cc + 1 < GNCHK) {
            A_LDG(cc + 1, aregs);
            B_ISSUE(cc + 1, buf ^ 1);
            CP_WAIT1();
        } else {
            CP_WAIT0();
        }
        __syncthreads();

        uint32_t bb = smb + buf * GBUF;
        uint32_t sAh = bb, sBh = bb + GPART, sBl = bb + 2 * GPART;

#pragma unroll
        for (int ks = 0; ks < 4; ks++) {
            uint32_t ah[2][4];
#pragma unroll
            for (int mf = 0; mf < 2; mf++) {
                uint32_t a = ((wm + mf * 16 + arow) * GLDA + ks * 16 + acol8) * 2;
                LDSM_X4(ah[mf][0], ah[mf][1], ah[mf][2], ah[mf][3], sAh + a);
            }
            uint32_t bh[4][2], bl[4][2];
#pragma unroll
            for (int nf2 = 0; nf2 < 2; nf2++) {
                uint32_t a = ((wn + nf2 * 16 + brow) * GLDA + ks * 16 + bcol8) * 2;
                uint32_t r0, r1, r2, r3;
                LDSM_X4(r0, r1, r2, r3, sBh + a);
                bh[nf2 * 2][0] = r0; bh[nf2 * 2][1] = r1;
                bh[nf2 * 2 + 1][0] = r2; bh[nf2 * 2 + 1][1] = r3;
                LDSM_X4(r0, r1, r2, r3, sBl + a);
                bl[nf2 * 2][0] = r0; bl[nf2 * 2][1] = r1;
                bl[nf2 * 2 + 1][0] = r2; bl[nf2 * 2 + 1][1] = r3;
            }
#pragma unroll
            for (int mf = 0; mf < 2; mf++)
#pragma unroll
                for (int nf = 0; nf < 4; nf++) {
                    MMA16816(c[mf][nf], ah[mf][0], ah[mf][1], ah[mf][2], ah[mf][3],
                             bh[nf][0], bh[nf][1]);
                    MMA16816(c[mf][nf], ah[mf][0], ah[mf][1], ah[mf][2], ah[mf][3],
                             bl[nf][0], bl[nf][1]);
                }
        }

        if (cc + 1 < GNCHK) A_STS(buf ^ 1, aregs);
        __syncthreads();
    }

    // Epilogue: stage f32 tile, bias+scale, emit fp16 (hi, and lo for K/V)
    float* sOut = (float*)smraw;
    int g = lane >> 2, t4 = lane & 3;
#pragma unroll
    for (int mf = 0; mf < 2; mf++) {
        int m0 = wm + mf * 16 + g;
#pragma unroll
        for (int nf = 0; nf < 4; nf++) {
            int col = wn + nf * 8 + t4 * 2;
            sOut[m0 * 128 + col]       = c[mf][nf][0];
            sOut[m0 * 128 + col + 1]   = c[mf][nf][1];
            sOut[(m0 + 8) * 128 + col]     = c[mf][nf][2];
            sOut[(m0 + 8) * 128 + col + 1] = c[mf][nf][3];
        }
    }
    __syncthreads();

    bool write_lo = (Ylo != (__half*)0);
#pragma unroll
    for (int it = 0; it < 8; it++) {
        int idx = tid + it * 512;
        int row = idx >> 5, c4 = (idx & 31) * 4;
        float4 o = *(float4*)(sOut + row * 128 + c4);
        const float* bp = bias + bn + c4;
        float y0 = (o.x + bp[0]) * scale;
        float y1 = (o.y + bp[1]) * scale;
        float y2 = (o.z + bp[2]) * scale;
        float y3 = (o.w + bp[3]) * scale;
        size_t off = (size_t)(bm + row) * Dm + bn + c4;
        if (write_lo) {
            uint32_t l01, l23;
            uint32_t h01 = split_h2(y0, y1, l01);
            uint32_t h23 = split_h2(y2, y3, l23);
            *(uint2*)(Yhi + off) = make_uint2(h01, h23);
            *(uint2*)(Ylo + off) = make_uint2(l01, l23);
        } else {
            uint32_t h01 = pack_h2(y0, y1);
            uint32_t h23 = pack_h2(y2, y3);
            *(uint2*)(Yhi + off) = make_uint2(h01, h23);
        }
    }
}

// ============ register-resident flash attention (fp16 split-2) =============
// S = Qh*Kh + Qh*Kl ;  O += Ph*Vh + Ph*Vl.  V loads via ldmatrix.x4.trans.
#define LDA 56
#define QARR (128 * LDA * 2)
#define KARR (64 * LDA * 2)
#define BUFB (4 * KARR)
#define ATTN_SMEM (QARR + 3 * BUFB)

__global__ __launch_bounds__(256, 2) void attn_reg_kernel(
    const __half* __restrict__ Qh_g,
    const __half* __restrict__ Kh_g, const __half* __restrict__ Kl_g,
    const __half* __restrict__ Vh_g, const __half* __restrict__ Vl_g,
    float* __restrict__ Og)
{
    extern __shared__ __align__(128) char smraw[];
    uint32_t smb = smem_u32(smraw);
    __half* Qh = (__half*)smraw;

    int qt = (int)gridDim.x - 1 - (int)blockIdx.x;
    int bh = blockIdx.y;
    int b = bh >> 4, h = bh & 15;
    int tid = threadIdx.x;
    int w = tid >> 5, lane = tid & 31;
    int rowbase = b * Sseq;
    int q0 = qt * 128;
    int hoff = h * DHh;
    int ntiles = 2 * qt + 2;

    {
#pragma unroll
        for (int it = 0; it < 6; it++) {
            int s = tid + it * 256;
            int arr = s / 384, rem = s - arr * 384;
            int r = rem / 6, c16 = rem - r * 6;
            const __half* src = (arr == 0) ? Kh_g : (arr == 1) ? Kl_g :
                                (arr == 2) ? Vh_g : Vl_g;
            const __half* ga = src + (size_t)(rowbase + r) * Dm + hoff + c16 * 8;
            uint32_t sa = smb + QARR + arr * KARR + r * (LDA * 2) + c16 * 16;
            CP_ASYNC16(sa, ga);
        }
        CP_COMMIT();
    }

    for (int s = tid; s < 768; s += 256) {
        int r = s / 6, c8 = (s % 6) * 8;
        *(uint4*)(Qh + r * LDA + c8) =
            *(const uint4*)(Qh_g + (size_t)(rowbase + q0 + r) * Dm + hoff + c8);
    }
    __syncthreads();

    int mat = lane >> 3;
    int qrow_loc = ((mat & 1) << 3) + (lane & 7);   // also V x4.trans row map
    int qcol8 = (mat >> 1) << 3;                    // also V x4.trans col-block
    int brow = ((mat >> 1) << 3) + (lane & 7);
    int bcol8 = (mat & 1) << 3;

    uint32_t qh[3][4];
#pragma unroll
    for (int ks = 0; ks < 3; ks++) {
        uint32_t a = smb + ((w * 16 + qrow_loc) * LDA + ks * 16 + qcol8) * 2;
        LDSM_X4(qh[ks][0], qh[ks][1], qh[ks][2], qh[ks][3], a);
    }

    int g = lane >> 2, t4 = lane & 3;

    float m0 = -1e30f, m1 = -1e30f, l0 = 0.f, l1 = 0.f;
    float o[6][4];
#pragma unroll
    for (int on = 0; on < 6; on++)
#pragma unroll
        for (int e = 0; e < 4; e++) o[on][e] = 0.f;

    for (int j = 0; j < ntiles; j++) {
        if (j + 1 < ntiles) {
            int k0n = (j + 1) * 64;
            uint32_t bb = smb + QARR + ((j + 1) % 3) * BUFB;
#pragma unroll
            for (int it = 0; it < 6; it++) {
                int s = tid + it * 256;
                int arr = s / 384, rem = s - arr * 384;
                int r = rem / 6, c16 = rem - r * 6;
                const __half* src = (arr == 0) ? Kh_g : (arr == 1) ? Kl_g :
                                    (arr == 2) ? Vh_g : Vl_g;
                const __half* ga = src + (size_t)(rowbase + k0n + r) * Dm + hoff + c16 * 8;
                uint32_t sa = bb + arr * KARR + r * (LDA * 2) + c16 * 16;
                CP_ASYNC16(sa, ga);
            }
            CP_COMMIT();
            CP_WAIT1();
        } else {
            CP_WAIT0();
        }
        __syncthreads();

        uint32_t bufb = smb + QARR + (j % 3) * BUFB;
        uint32_t bufKh = bufb, bufKl = bufb + KARR;
        uint32_t bufVh = bufb + 2 * KARR, bufVl = bufb + 3 * KARR;

        // ---- S = Qh Kh^T + Qh Kl^T ----
        float sc[8][4];
#pragma unroll
        for (int jn2 = 0; jn2 < 4; jn2++) {
#pragma unroll
            for (int e = 0; e < 4; e++) { sc[2*jn2][e] = 0.f; sc[2*jn2+1][e] = 0.f; }
#pragma unroll
            for (int ks = 0; ks < 3; ks++) {
                uint32_t a = ((jn2 * 16 + brow) * LDA + ks * 16 + bcol8) * 2;
                uint32_t kh0, kh1, kh2, kh3, kl0, kl1, kl2, kl3;
                LDSM_X4(kh0, kh1, kh2, kh3, bufKh + a);
                LDSM_X4(kl0, kl1, kl2, kl3, bufKl + a);
                MMA16816(sc[2*jn2],   qh[ks][0], qh[ks][1], qh[ks][2], qh[ks][3], kh0, kh1);
                MMA16816(sc[2*jn2],   qh[ks][0], qh[ks][1], qh[ks][2], qh[ks][3], kl0, kl1);
                MMA16816(sc[2*jn2+1], qh[ks][0], qh[ks][1], qh[ks][2], qh[ks][3], kh2, kh3);
                MMA16816(sc[2*jn2+1], qh[ks][0], qh[ks][1], qh[ks][2], qh[ks][3], kl2, kl3);
            }
        }

        int k0 = j * 64;
        if (j >= 2 * qt) {
            int qg0 = q0 + w * 16 + g;
#pragma unroll
            for (int jn = 0; jn < 8; jn++) {
                int cix = k0 + jn * 8 + 2 * t4;
                if (qg0 < cix)     sc[jn][0] = -1e30f;
                if (qg0 < cix + 1) sc[jn][1] = -1e30f;
                if (qg0 + 8 < cix)     sc[jn][2] = -1e30f;
                if (qg0 + 8 < cix + 1) sc[jn][3] = -1e30f;
            }
        }

        float mx0 = -1e30f, mx1 = -1e30f;
#pragma unroll
        for (int jn = 0; jn < 8; jn++) {
            mx0 = fmaxf(mx0, fmaxf(sc[jn][0], sc[jn][1]));
            mx1 = fmaxf(mx1, fmaxf(sc[jn][2], sc[jn][3]));
        }
        mx0 = fmaxf(mx0, __shfl_xor_sync(0xffffffffu, mx0, 1));
        mx0 = fmaxf(mx0, __shfl_xor_sync(0xffffffffu, mx0, 2));
        mx1 = fmaxf(mx1, __shfl_xor_sync(0xffffffffu, mx1, 1));
        mx1 = fmaxf(mx1, __shfl_xor_sync(0xffffffffu, mx1, 2));
        float mn0 = fmaxf(m0, mx0), mn1 = fmaxf(m1, mx1);
        float al0 = ex2(m0 - mn0), al1 = ex2(m1 - mn1);
        m0 = mn0; m1 = mn1;
        float ps0 = 0.f, ps1 = 0.f;
#pragma unroll
        for (int jn = 0; jn < 8; jn++) {
            sc[jn][0] = ex2(sc[jn][0] - mn0);
            sc[jn][1] = ex2(sc[jn][1] - mn0);
            sc[jn][2] = ex2(sc[jn][2] - mn1);
            sc[jn][3] = ex2(sc[jn][3] - mn1);
            ps0 += sc[jn][0] + sc[jn][1];
            ps1 += sc[jn][2] + sc[jn][3];
        }
        ps0 += __shfl_xor_sync(0xffffffffu, ps0, 1);
        ps0 += __shfl_xor_sync(0xffffffffu, ps0, 2);
        ps1 += __shfl_xor_sync(0xffffffffu, ps1, 1);
        ps1 += __shfl_xor_sync(0xffffffffu, ps1, 2);
        l0 = l0 * al0 + ps0;
        l1 = l1 * al1 + ps1;

#pragma unroll
        for (int on = 0; on < 6; on++) {
            o[on][0] *= al0; o[on][1] *= al0;
            o[on][2] *= al1; o[on][3] *= al1;
        }
        // ---- O += P Vh + P Vl : V via x4.trans (2 n8-tiles per load) ----
#pragma unroll
        for (int ks = 0; ks < 4; ks++) {
            uint32_t pa[4];
            pa[0] = pack_h2(sc[2*ks][0],   sc[2*ks][1]);
            pa[1] = pack_h2(sc[2*ks][2],   sc[2*ks][3]);
            pa[2] = pack_h2(sc[2*ks+1][0], sc[2*ks+1][1]);
            pa[3] = pack_h2(sc[2*ks+1][2], sc[2*ks+1][3]);
#pragma unroll
            for (int on2 = 0; on2 < 3; on2++) {
                uint32_t va = ((ks * 16 + qrow_loc) * LDA + on2 * 16 + qcol8) * 2;
                uint32_t vh0, vh1, vh2, vh3, vl0, vl1, vl2, vl3;
                LDSM_X4T(vh0, vh1, vh2, vh3, bufVh + va);
                LDSM_X4T(vl0, vl1, vl2, vl3, bufVl + va);
                MMA16816(o[2*on2],   pa[0], pa[1], pa[2], pa[3], vh0, vh1);
                MMA16816(o[2*on2],   pa[0], pa[1], pa[2], pa[3], vl0, vl1);
                MMA16816(o[2*on2+1], pa[0], pa[1], pa[2], pa[3], vh2, vh3);
                MMA16816(o[2*on2+1], pa[0], pa[1], pa[2], pa[3], vl2, vl3);
            }
        }
        __syncthreads();
    }

    float inv0 = 1.f / l0, inv1 = 1.f / l1;
    float* op0 = Og + (size_t)(rowbase + q0 + w * 16 + g) * Dm + hoff + 2 * t4;
    float* op1 = op0 + 8 * Dm;
#pragma unroll
    for (int on = 0; on < 6; on++) {
        float2 r0 = make_float2(o[on][0] * inv0, o[on][1] * inv0);
        float2 r1 = make_float2(o[on][2] * inv1, o[on][3] * inv1);
        *(float2*)(op0 + on * 8) = r0;
        *(float2*)(op1 + on * 8) = r1;
    }
}

// ---------------------------------------------------------------------------
// LayerNorm: 192 threads/row, float4 per thread.
// ---------------------------------------------------------------------------
__global__ __launch_bounds__(192) void ln_kernel(
    const float* __restrict__ X, const float* __restrict__ gamma,
    const float* __restrict__ beta, float* __restrict__ Y)
{
    int row = blockIdx.x;
    int tid = threadIdx.x;
    const float* x = X + (size_t)row * Dm;

    float4 v = *(const float4*)(x + tid * 4);
    float s  = v.x + v.y + v.z + v.w;
    float sq = v.x * v.x + v.y * v.y + v.z * v.z + v.w * v.w;

#pragma unroll
    for (int off = 16; off > 0; off >>= 1) {
        s  += __shfl_xor_sync(0xffffffffu, s, off);
        sq += __shfl_xor_sync(0xffffffffu, sq, off);
    }
    __shared__ float red_s[6], red_q[6];
    int wid = tid >> 5, lid = tid & 31;
    if (lid == 0) { red_s[wid] = s; red_q[wid] = sq; }
    __syncthreads();
    float ts = 0.f, tq = 0.f;
#pragma unroll
    for (int i = 0; i < 6; i++) { ts += red_s[i]; tq += red_q[i]; }
    float mu  = ts * (1.f / Dm);
    float var = tq * (1.f / Dm) - mu * mu;
    float inv = rsqrtf(var + 1e-3f);

    float4 gmv = *(const float4*)(gamma + tid * 4);
    float4 btv = *(const float4*)(beta + tid * 4);
    float4 yv;
    yv.x = (v.x - mu) * inv * gmv.x + btv.x;
    yv.y = (v.y - mu) * inv * gmv.y + btv.y;
    yv.z = (v.z - mu) * inv * gmv.z + btv.z;
    yv.w = (v.w - mu) * inv * gmv.w + btv.w;
    *(float4*)(Y + (size_t)row * Dm + tid * 4) = yv;
}

// ---------------------------------------------------------------------------
extern "C" void kernel_launch(void* const* d_in, const int* in_sizes, int n_in,
                              void* d_out, int out_size)
{
    const float* q     = (const float*)d_in[0];
    const float* k     = (const float*)d_in[1];
    const float* v     = (const float*)d_in[2];
    const float* Wq    = (const float*)d_in[3];
    const float* bq    = (const float*)d_in[4];
    const float* Wk    = (const float*)d_in[5];
    const float* bk    = (const float*)d_in[6];
    const float* Wv    = (const float*)d_in[7];
    const float* bv    = (const float*)d_in[8];
    const float* gamma = (const float*)d_in[9];
    const float* beta  = (const float*)d_in[10];
    float* out = (float*)d_out;

    float* Og;
    __half *whi, *wlo, *qhi, *khi, *klo, *vhi, *vlo;
    cudaGetSymbolAddress((void**)&Og, g_O);
    cudaGetSymbolAddress((void**)&whi, g_Wthi);
    cudaGetSymbolAddress((void**)&wlo, g_Wtlo);
    cudaGetSymbolAddress((void**)&qhi, g_Qhi);
    cudaGetSymbolAddress((void**)&khi, g_Khi);
    cudaGetSymbolAddress((void**)&klo, g_Klo);
    cudaGetSymbolAddress((void**)&vhi, g_Vhi);
    cudaGetSymbolAddress((void**)&vlo, g_Vlo);

    cudaFuncSetAttribute(gemm_mma_kernel, cudaFuncAttributeMaxDynamicSharedMemorySize,
                         GEMM_SMEM_BYTES);
    cudaFuncSetAttribute(attn_reg_kernel, cudaFuncAttributeMaxDynamicSharedMemorySize,
                         ATTN_SMEM);

    convert_w_kernel<<<dim3(Dm / 32, Dm / 32, 3), dim3(32, 8)>>>(Wq, Wk, Wv, whi, wlo);

    gemm_mma_kernel<<<dim3(Dm / 128, NROWS / 128, 3), 512, GEMM_SMEM_BYTES>>>(
        q, k, v, whi, wlo, bq, bk, bv, qhi, khi, klo, vhi, vlo);

    attn_reg_kernel<<<dim3(Sseq / 128, Bsz * Hh), 256, ATTN_SMEM>>>(
        qhi, khi, klo, vhi, vlo, Og);

    ln_kernel<<<NROWS, 192>>>(Og, gamma, beta, out);
}

// round 16
// speedup vs baseline: 1.0777x; 1.0502x over previous
#include <cuda_runtime.h>
#include <cuda_fp16.h>
#include <math.h>
#include <stdint.h>

#define Bsz   4
#define Sseq  2048
#define Dm    768
#define Hh    16
#define DHh   48
#define NROWS (Bsz * Sseq)
#define XELEMS ((size_t)NROWS * Dm)
#define WELEMS ((size_t)Dm * Dm)

// softmax scale (1/sqrt(48)) * log2(e): folded into Q projection; exp2 in softmax
#define QSCALE 0.2082351f

// Scratch (__device__ globals per allocation-free rule)
__device__ float g_O[NROWS * Dm];
__device__ __half g_Wthi[3 * WELEMS];   // transposed W [n][k], fp16 hi
__device__ __half g_Wtlo[3 * WELEMS];   // fp16 residual
__device__ __half g_Qhi[XELEMS];        // Q needs hi only (A-side)
__device__ __half g_Khi[XELEMS];
__device__ __half g_Klo[XELEMS];
__device__ __half g_Vhi[XELEMS];
__device__ __half g_Vlo[XELEMS];

// ============================ PTX helpers ==================================
__device__ __forceinline__ uint32_t smem_u32(const void* p) {
    uint32_t a;
    asm("{ .reg .u64 t; cvta.to.shared.u64 t, %1; cvt.u32.u64 %0, t; }" : "=r"(a) : "l"(p));
    return a;
}
__device__ __forceinline__ float ex2(float x) {
    float y; asm("ex2.approx.ftz.f32 %0, %1;" : "=f"(y) : "f"(x)); return y;
}
#define MMA16816(C, a0, a1, a2, a3, b0, b1)                                   \
    asm volatile("mma.sync.aligned.m16n8k16.row.col.f32.f16.f16.f32 "         \
        "{%0,%1,%2,%3}, {%4,%5,%6,%7}, {%8,%9}, {%0,%1,%2,%3};"               \
        : "+f"((C)[0]), "+f"((C)[1]), "+f"((C)[2]), "+f"((C)[3])              \
        : "r"(a0), "r"(a1), "r"(a2), "r"(a3), "r"(b0), "r"(b1))
#define LDSM_X4(r0, r1, r2, r3, addr)                                         \
    asm volatile("ldmatrix.sync.aligned.m8n8.x4.shared.b16 {%0,%1,%2,%3}, [%4];" \
        : "=r"(r0), "=r"(r1), "=r"(r2), "=r"(r3) : "r"(addr))
#define LDSM_X4T(r0, r1, r2, r3, addr)                                        \
    asm volatile("ldmatrix.sync.aligned.m8n8.x4.trans.shared.b16 {%0,%1,%2,%3}, [%4];" \
        : "=r"(r0), "=r"(r1), "=r"(r2), "=r"(r3) : "r"(addr))
#define CP_ASYNC16(sa, ga)                                                    \
    asm volatile("cp.async.cg.shared.global [%0], [%1], 16;" :: "r"(sa), "l"(ga))
#define CP_COMMIT() asm volatile("cp.async.commit_group;" ::: "memory")
#define CP_WAIT1()  asm volatile("cp.async.wait_group 1;" ::: "memory")
#define CP_WAIT0()  asm volatile("cp.async.wait_group 0;" ::: "memory")

// Pack two floats to fp16x2 (x -> low half, y -> high half)
__device__ __forceinline__ uint32_t pack_h2(float x, float y) {
    uint32_t r;
    asm("cvt.rn.f16x2.f32 %0, %1, %2;" : "=r"(r) : "f"(y), "f"(x));
    return r;
}
// fp16 split: hi = RN(x), lo = RN(x - hi)
__device__ __forceinline__ uint32_t split_h2(float x, float y, uint32_t& lo) {
    uint32_t hi = pack_h2(x, y);
    __half2 h2 = *(__half2*)&hi;
    float xl = x - __low2float(h2);
    float yl = y - __high2float(h2);
    lo = pack_h2(xl, yl);
    return hi;
}

// ============================ W converter ==================================
__global__ __launch_bounds__(256) void convert_w_kernel(
    const float* __restrict__ wq, const float* __restrict__ wk,
    const float* __restrict__ wv,
    __half* __restrict__ hi, __half* __restrict__ lo)
{
    __shared__ float tile[32][33];
    int z = blockIdx.z;
    const float* W = (z == 0) ? wq : (z == 1) ? wk : wv;
    size_t base = (size_t)z * WELEMS;
    int tx = threadIdx.x, ty = threadIdx.y;
    int bx = blockIdx.x, by = blockIdx.y;
#pragma unroll
    for (int i = 0; i < 4; i++) {
        int kk = by * 32 + ty + i * 8;
        int n = bx * 32 + tx;
        tile[ty + i * 8][tx] = W[kk * Dm + n];
    }
    __syncthreads();
#pragma unroll
    for (int i = 0; i < 4; i++) {
        int n = bx * 32 + ty + i * 8;
        int kk = by * 32 + tx;
        float v = tile[tx][ty + i * 8];
        __half h = __float2half_rn(v);
        __half l = __float2half_rn(v - __half2float(h));
        hi[base + n * Dm + kk] = h;
        lo[base + n * Dm + kk] = l;
    }
}

// ================= batched mma.sync GEMM (fp16 split-2) ====================
// Y = (X@W + bias)*scale. A = fp16(X) in-kernel (hi only); B = Whi + Wlo.
// D = Ah*Bh + Ah*Bl. CTA 128x128, BK=64, 512 threads, warp tile 32x32.
#define GBK   64
#define GLDA  72                              // 64 + 8 pad (144 B rows)
#define GPART (128 * GLDA * 2)                // 18432 B per operand array
#define GBUF  (3 * GPART)                     // Ah, Bh, Bl = 55296 B
#define GEMM_SMEM_BYTES (2 * GBUF)            // 110592 B (epilogue 64 KB fits)
#define GNCHK (Dm / GBK)                      // 12

__global__ __launch_bounds__(512) void gemm_mma_kernel(
    const float* __restrict__ xq, const float* __restrict__ xk,
    const float* __restrict__ xv,
    const __half* __restrict__ whi, const __half* __restrict__ wlo,
    const float* __restrict__ bq, const float* __restrict__ bk,
    const float* __restrict__ bv,
    __half* __restrict__ qhi,
    __half* __restrict__ khi, __half* __restrict__ klo,
    __half* __restrict__ vhi, __half* __restrict__ vlo)
{
    extern __shared__ __align__(128) char smraw[];
    uint32_t smb = smem_u32(smraw);
    int z = blockIdx.z;
    const float* Af = (z == 0) ? xq : (z == 1) ? xk : xv;
    const __half* Bhi = whi + (size_t)z * WELEMS;
    const __half* Blo = wlo + (size_t)z * WELEMS;
    const float* bias = (z == 0) ? bq : (z == 1) ? bk : bv;
    __half* Yhi = (z == 0) ? qhi : (z == 1) ? khi : vhi;
    __half* Ylo = (z == 0) ? (__half*)0 : (z == 1) ? klo : vlo;
    float scale = (z == 0) ? QSCALE : 1.0f;

    int tid = threadIdx.x;
    int w = tid >> 5, lane = tid & 31;
    int bm = blockIdx.y * 128;
    int bn = blockIdx.x * 128;

    int wm = (w >> 2) * 32;
    int wn = (w & 3) * 32;

    int mat = lane >> 3;
    int arow = ((mat & 1) << 3) + (lane & 7);
    int acol8 = (mat >> 1) << 3;
    int brow = ((mat >> 1) << 3) + (lane & 7);
    int bcol8 = (mat & 1) << 3;

    // A loader: 128 rows x 16 float4/row = 2048 -> 4/thread
    int a_row0 = tid >> 4, a_f4 = (tid & 15);

    float c[2][4][4];
#pragma unroll
    for (int mf = 0; mf < 2; mf++)
#pragma unroll
        for (int nf = 0; nf < 4; nf++)
#pragma unroll
            for (int e = 0; e < 4; e++) c[mf][nf][e] = 0.f;

// B: 2 arrays x 128 rows x 8 segs(16B) = 2048 -> 4/thread
#define B_ISSUE(c0, bufsel) do {                                              \
    int k0_ = (c0) * GBK;                                                     \
    uint32_t bb_ = smb + (bufsel) * GBUF;                                     \
    _Pragma("unroll")                                                         \
    for (int it = 0; it < 4; it++) {                                          \
        int idx = tid + it * 512;                                             \
        int part = idx >> 10;                                                 \
        int rem = idx & 1023;                                                 \
        int row = rem >> 3, seg = rem & 7;                                    \
        const __half* ga = (part ? Blo : Bhi) +                               \
            (size_t)(bn + row) * Dm + k0_ + seg * 8;                          \
        uint32_t sa = bb_ + (1 + part) * GPART + row * (GLDA * 2) + seg * 16; \
        CP_ASYNC16(sa, ga);                                                   \
    }                                                                         \
    CP_COMMIT();                                                              \
} while (0)

#define A_LDG(c0, regs) do {                                                  \
    int k0_ = (c0) * GBK;                                                     \
    _Pragma("unroll")                                                         \
    for (int it = 0; it < 4; it++)                                            \
        (regs)[it] = *(const float4*)(Af +                                    \
            (size_t)(bm + a_row0 + it * 32) * Dm + k0_ + a_f4 * 4);           \
} while (0)

#define A_STS(bufsel, regs) do {                                              \
    _Pragma("unroll")                                                         \
    for (int it = 0; it < 4; it++) {                                          \
        int row = a_row0 + it * 32;                                           \
        float4 v = (regs)[it];                                                \
        uint32_t h01 = pack_h2(v.x, v.y);                                     \
        uint32_t h23 = pack_h2(v.z, v.w);                                     \
        uint32_t off = row * (GLDA * 2) + a_f4 * 8;                           \
        *(uint2*)(smraw + (bufsel) * GBUF + off) = make_uint2(h01, h23);      \
    }                                                                         \
} while (0)

    float4 aregs[4];
    B_ISSUE(0, 0);
    A_LDG(0, aregs);
    A_STS(0, aregs);

    for (int cc = 0; cc < GNCHK; cc++) {
        int buf = cc & 1;
        if (cc + 1 < GNCHK) {
            A_LDG(cc + 1, aregs);
            B_ISSUE(cc + 1, buf ^ 1);
            CP_WAIT1();
        } else {
            CP_WAIT0();
        }
        __syncthreads();

        uint32_t bb = smb + buf * GBUF;
        uint32_t sAh = bb, sBh = bb + GPART, sBl = bb + 2 * GPART;

#pragma unroll
        for (int ks = 0; ks < 4; ks++) {
            uint32_t ah[2][4];
#pragma unroll
            for (int mf = 0; mf < 2; mf++) {
                uint32_t a = ((wm + mf * 16 + arow) * GLDA + ks * 16 + acol8) * 2;
                LDSM_X4(ah[mf][0], ah[mf][1], ah[mf][2], ah[mf][3], sAh + a);
            }
            uint32_t bh[4][2], bl[4][2];
#pragma unroll
            for (int nf2 = 0; nf2 < 2; nf2++) {
                uint32_t a = ((wn + nf2 * 16 + brow) * GLDA + ks * 16 + bcol8) * 2;
                uint32_t r0, r1, r2, r3;
                LDSM_X4(r0, r1, r2, r3, sBh + a);
                bh[nf2 * 2][0] = r0; bh[nf2 * 2][1] = r1;
                bh[nf2 * 2 + 1][0] = r2; bh[nf2 * 2 + 1][1] = r3;
                LDSM_X4(r0, r1, r2, r3, sBl + a);
                bl[nf2 * 2][0] = r0; bl[nf2 * 2][1] = r1;
                bl[nf2 * 2 + 1][0] = r2; bl[nf2 * 2 + 1][1] = r3;
            }
#pragma unroll
            for (int mf = 0; mf < 2; mf++)
#pragma unroll
                for (int nf = 0; nf < 4; nf++) {
                    MMA16816(c[mf][nf], ah[mf][0], ah[mf][1], ah[mf][2], ah[mf][3],
                             bh[nf][0], bh[nf][1]);
                    MMA16816(c[mf][nf], ah[mf][0], ah[mf][1], ah[mf][2], ah[mf][3],
                             bl[nf][0], bl[nf][1]);
                }
        }

        if (cc + 1 < GNCHK) A_STS(buf ^ 1, aregs);
        __syncthreads();
    }

    // Epilogue: stage f32 tile, bias+scale, emit fp16 (hi, and lo for K/V)
    float* sOut = (float*)smraw;
    int g = lane >> 2, t4 = lane & 3;
#pragma unroll
    for (int mf = 0; mf < 2; mf++) {
        int m0 = wm + mf * 16 + g;
#pragma unroll
        for (int nf = 0; nf < 4; nf++) {
            int col = wn + nf * 8 + t4 * 2;
            sOut[m0 * 128 + col]       = c[mf][nf][0];
            sOut[m0 * 128 + col + 1]   = c[mf][nf][1];
            sOut[(m0 + 8) * 128 + col]     = c[mf][nf][2];
            sOut[(m0 + 8) * 128 + col + 1] = c[mf][nf][3];
        }
    }
    __syncthreads();

    bool write_lo = (Ylo != (__half*)0);
#pragma unroll
    for (int it = 0; it < 8; it++) {
        int idx = tid + it * 512;
        int row = idx >> 5, c4 = (idx & 31) * 4;
        float4 o = *(float4*)(sOut + row * 128 + c4);
        const float* bp = bias + bn + c4;
        float y0 = (o.x + bp[0]) * scale;
        float y1 = (o.y + bp[1]) * scale;
        float y2 = (o.z + bp[2]) * scale;
        float y3 = (o.w + bp[3]) * scale;
        size_t off = (size_t)(bm + row) * Dm + bn + c4;
        if (write_lo) {
            uint32_t l01, l23;
            uint32_t h01 = split_h2(y0, y1, l01);
            uint32_t h23 = split_h2(y2, y3, l23);
            *(uint2*)(Yhi + off) = make_uint2(h01, h23);
            *(uint2*)(Ylo + off) = make_uint2(l01, l23);
        } else {
            uint32_t h01 = pack_h2(y0, y1);
            uint32_t h23 = pack_h2(y2, y3);
            *(uint2*)(Yhi + off) = make_uint2(h01, h23);
        }
    }
}

// ============ register-resident flash attention (fp16 split-2) =============
// S = Qh*Kh + Qh*Kl ;  O += Ph*Vh + Ph*Vl.  V loads via ldmatrix.x4.trans.
// One barrier per KV tile (3-deep ring makes the trailing barrier redundant).
#define LDA 56
#define QARR (128 * LDA * 2)
#define KARR (64 * LDA * 2)
#define BUFB (4 * KARR)
#define ATTN_SMEM (QARR + 3 * BUFB)

__global__ __launch_bounds__(256, 2) void attn_reg_kernel(
    const __half* __restrict__ Qh_g,
    const __half* __restrict__ Kh_g, const __half* __restrict__ Kl_g,
    const __half* __restrict__ Vh_g, const __half* __restrict__ Vl_g,
    float* __restrict__ Og)
{
    extern __shared__ __align__(128) char smraw[];
    uint32_t smb = smem_u32(smraw);
    __half* Qh = (__half*)smraw;

    int qt = (int)gridDim.x - 1 - (int)blockIdx.x;
    int bh = blockIdx.y;
    int b = bh >> 4, h = bh & 15;
    int tid = threadIdx.x;
    int w = tid >> 5, lane = tid & 31;
    int rowbase = b * Sseq;
    int q0 = qt * 128;
    int hoff = h * DHh;
    int ntiles = 2 * qt + 2;

    {
#pragma unroll
        for (int it = 0; it < 6; it++) {
            int s = tid + it * 256;
            int arr = s / 384, rem = s - arr * 384;
            int r = rem / 6, c16 = rem - r * 6;
            const __half* src = (arr == 0) ? Kh_g : (arr == 1) ? Kl_g :
                                (arr == 2) ? Vh_g : Vl_g;
            const __half* ga = src + (size_t)(rowbase + r) * Dm + hoff + c16 * 8;
            uint32_t sa = smb + QARR + arr * KARR + r * (LDA * 2) + c16 * 16;
            CP_ASYNC16(sa, ga);
        }
        CP_COMMIT();
    }

    for (int s = tid; s < 768; s += 256) {
        int r = s / 6, c8 = (s % 6) * 8;
        *(uint4*)(Qh + r * LDA + c8) =
            *(const uint4*)(Qh_g + (size_t)(rowbase + q0 + r) * Dm + hoff + c8);
    }
    __syncthreads();

    int mat = lane >> 3;
    int qrow_loc = ((mat & 1) << 3) + (lane & 7);   // also V x4.trans row map
    int qcol8 = (mat >> 1) << 3;                    // also V x4.trans col-block
    int brow = ((mat >> 1) << 3) + (lane & 7);
    int bcol8 = (mat & 1) << 3;

    uint32_t qh[3][4];
#pragma unroll
    for (int ks = 0; ks < 3; ks++) {
        uint32_t a = smb + ((w * 16 + qrow_loc) * LDA + ks * 16 + qcol8) * 2;
        LDSM_X4(qh[ks][0], qh[ks][1], qh[ks][2], qh[ks][3], a);
    }

    int g = lane >> 2, t4 = lane & 3;

    float m0 = -1e30f, m1 = -1e30f, l0 = 0.f, l1 = 0.f;
    float o[6][4];
#pragma unroll
    for (int on = 0; on < 6; on++)
#pragma unroll
        for (int e = 0; e < 4; e++) o[on][e] = 0.f;

    for (int j = 0; j < ntiles; j++) {
        if (j + 1 < ntiles) {
            int k0n = (j + 1) * 64;
            uint32_t bb = smb + QARR + ((j + 1) % 3) * BUFB;
#pragma unroll
            for (int it = 0; it < 6; it++) {
                int s = tid + it * 256;
                int arr = s / 384, rem = s - arr * 384;
                int r = rem / 6, c16 = rem - r * 6;
                const __half* src = (arr == 0) ? Kh_g : (arr == 1) ? Kl_g :
                                    (arr == 2) ? Vh_g : Vl_g;
                const __half* ga = src + (size_t)(rowbase + k0n + r) * Dm + hoff + c16 * 8;
                uint32_t sa = bb + arr * KARR + r * (LDA * 2) + c16 * 16;
                CP_ASYNC16(sa, ga);
            }
            CP_COMMIT();
            CP_WAIT1();
        } else {
            CP_WAIT0();
        }
        __syncthreads();   // sole barrier per tile: protects slot j%3 for reuse at j+2

        // Fully-masked warp skip: second diagonal tile, rows entirely above diag
        if (j == 2 * qt + 1 && w < 4) continue;

        uint32_t bufb = smb + QARR + (j % 3) * BUFB;
        uint32_t bufKh = bufb, bufKl = bufb + KARR;
        uint32_t bufVh = bufb + 2 * KARR, bufVl = bufb + 3 * KARR;

        // ---- S = Qh Kh^T + Qh Kl^T ----
        float sc[8][4];
#pragma unroll
        for (int jn2 = 0; jn2 < 4; jn2++) {
#pragma unroll
            for (int e = 0; e < 4; e++) { sc[2*jn2][e] = 0.f; sc[2*jn2+1][e] = 0.f; }
#pragma unroll
            for (int ks = 0; ks < 3; ks++) {
                uint32_t a = ((jn2 * 16 + brow) * LDA + ks * 16 + bcol8) * 2;
                uint32_t kh0, kh1, kh2, kh3, kl0, kl1, kl2, kl3;
                LDSM_X4(kh0, kh1, kh2, kh3, bufKh + a);
                LDSM_X4(kl0, kl1, kl2, kl3, bufKl + a);
                MMA16816(sc[2*jn2],   qh[ks][0], qh[ks][1], qh[ks][2], qh[ks][3], kh0, kh1);
                MMA16816(sc[2*jn2],   qh[ks][0], qh[ks][1], qh[ks][2], qh[ks][3], kl0, kl1);
                MMA16816(sc[2*jn2+1], qh[ks][0], qh[ks][1], qh[ks][2], qh[ks][3], kh2, kh3);
                MMA16816(sc[2*jn2+1], qh[ks][0], qh[ks][1], qh[ks][2], qh[ks][3], kl2, kl3);
            }
        }

        int k0 = j * 64;
        if (j >= 2 * qt) {
            int qg0 = q0 + w * 16 + g;
#pragma unroll
            for (int jn = 0; jn < 8; jn++) {
                int cix = k0 + jn * 8 + 2 * t4;
                if (qg0 < cix)     sc[jn][0] = -1e30f;
                if (qg0 < cix + 1) sc[jn][1] = -1e30f;
                if (qg0 + 8 < cix)     sc[jn][2] = -1e30f;
                if (qg0 + 8 < cix + 1) sc[jn][3] = -1e30f;
            }
        }

        float mx0 = -1e30f, mx1 = -1e30f;
#pragma unroll
        for (int jn = 0; jn < 8; jn++) {
            mx0 = fmaxf(mx0, fmaxf(sc[jn][0], sc[jn][1]));
            mx1 = fmaxf(mx1, fmaxf(sc[jn][2], sc[jn][3]));
        }
        mx0 = fmaxf(mx0, __shfl_xor_sync(0xffffffffu, mx0, 1));
        mx0 = fmaxf(mx0, __shfl_xor_sync(0xffffffffu, mx0, 2));
        mx1 = fmaxf(mx1, __shfl_xor_sync(0xffffffffu, mx1, 1));
        mx1 = fmaxf(mx1, __shfl_xor_sync(0xffffffffu, mx1, 2));
        float mn0 = fmaxf(m0, mx0), mn1 = fmaxf(m1, mx1);
        float al0 = ex2(m0 - mn0), al1 = ex2(m1 - mn1);
        m0 = mn0; m1 = mn1;
        float ps0 = 0.f, ps1 = 0.f;
#pragma unroll
        for (int jn = 0; jn < 8; jn++) {
            sc[jn][0] = ex2(sc[jn][0] - mn0);
            sc[jn][1] = ex2(sc[jn][1] - mn0);
            sc[jn][2] = ex2(sc[jn][2] - mn1);
            sc[jn][3] = ex2(sc[jn][3] - mn1);
            ps0 += sc[jn][0] + sc[jn][1];
            ps1 += sc[jn][2] + sc[jn][3];
        }
        ps0 += __shfl_xor_sync(0xffffffffu, ps0, 1);
        ps0 += __shfl_xor_sync(0xffffffffu, ps0, 2);
        ps1 += __shfl_xor_sync(0xffffffffu, ps1, 1);
        ps1 += __shfl_xor_sync(0xffffffffu, ps1, 2);
        l0 = l0 * al0 + ps0;
        l1 = l1 * al1 + ps1;

#pragma unroll
        for (int on = 0; on < 6; on++) {
            o[on][0] *= al0; o[on][1] *= al0;
            o[on][2] *= al1; o[on][3] *= al1;
        }
        // ---- O += P Vh + P Vl : V via x4.trans (2 n8-tiles per load) ----
#pragma unroll
        for (int ks = 0; ks < 4; ks++) {
            uint32_t pa[4];
            pa[0] = pack_h2(sc[2*ks][0],   sc[2*ks][1]);
            pa[1] = pack_h2(sc[2*ks][2],   sc[2*ks][3]);
            pa[2] = pack_h2(sc[2*ks+1][0], sc[2*ks+1][1]);
            pa[3] = pack_h2(sc[2*ks+1][2], sc[2*ks+1][3]);
#pragma unroll
            for (int on2 = 0; on2 < 3; on2++) {
                uint32_t va = ((ks * 16 + qrow_loc) * LDA + on2 * 16 + qcol8) * 2;
                uint32_t vh0, vh1, vh2, vh3, vl0, vl1, vl2, vl3;
                LDSM_X4T(vh0, vh1, vh2, vh3, bufVh + va);
                LDSM_X4T(vl0, vl1, vl2, vl3, bufVl + va);
                MMA16816(o[2*on2],   pa[0], pa[1], pa[2], pa[3], vh0, vh1);
                MMA16816(o[2*on2],   pa[0], pa[1], pa[2], pa[3], vl0, vl1);
                MMA16816(o[2*on2+1], pa[0], pa[1], pa[2], pa[3], vh2, vh3);
                MMA16816(o[2*on2+1], pa[0], pa[1], pa[2], pa[3], vl2, vl3);
            }
        }
    }

    float inv0 = 1.f / l0, inv1 = 1.f / l1;
    float* op0 = Og + (size_t)(rowbase + q0 + w * 16 + g) * Dm + hoff + 2 * t4;
    float* op1 = op0 + 8 * Dm;
#pragma unroll
    for (int on = 0; on < 6; on++) {
        float2 r0 = make_float2(o[on][0] * inv0, o[on][1] * inv0);
        float2 r1 = make_float2(o[on][2] * inv1, o[on][3] * inv1);
        *(float2*)(op0 + on * 8) = r0;
        *(float2*)(op1 + on * 8) = r1;
    }
}

// ---------------------------------------------------------------------------
// LayerNorm: 192 threads/row, float4 per thread.
// ---------------------------------------------------------------------------
__global__ __launch_bounds__(192) void ln_kernel(
    const float* __restrict__ X, const float* __restrict__ gamma,
    const float* __restrict__ beta, float* __restrict__ Y)
{
    int row = blockIdx.x;
    int tid = threadIdx.x;
    const float* x = X + (size_t)row * Dm;

    float4 v = *(const float4*)(x + tid * 4);
    float s  = v.x + v.y + v.z + v.w;
    float sq = v.x * v.x + v.y * v.y + v.z * v.z + v.w * v.w;

#pragma unroll
    for (int off = 16; off > 0; off >>= 1) {
        s  += __shfl_xor_sync(0xffffffffu, s, off);
        sq += __shfl_xor_sync(0xffffffffu, sq, off);
    }
    __shared__ float red_s[6], red_q[6];
    int wid = tid >> 5, lid = tid & 31;
    if (lid == 0) { red_s[wid] = s; red_q[wid] = sq; }
    __syncthreads();
    float ts = 0.f, tq = 0.f;
#pragma unroll
    for (int i = 0; i < 6; i++) { ts += red_s[i]; tq += red_q[i]; }
    float mu  = ts * (1.f / Dm);
    float var = tq * (1.f / Dm) - mu * mu;
    float inv = rsqrtf(var + 1e-3f);

    float4 gmv = *(const float4*)(gamma + tid * 4);
    float4 btv = *(const float4*)(beta + tid * 4);
    float4 yv;
    yv.x = (v.x - mu) * inv * gmv.x + btv.x;
    yv.y = (v.y - mu) * inv * gmv.y + btv.y;
    yv.z = (v.z - mu) * inv * gmv.z + btv.z;
    yv.w = (v.w - mu) * inv * gmv.w + btv.w;
    *(float4*)(Y + (size_t)row * Dm + tid * 4) = yv;
}

// ---------------------------------------------------------------------------
extern "C" void kernel_launch(void* const* d_in, const int* in_sizes, int n_in,
                              void* d_out, int out_size)
{
    const float* q     = (const float*)d_in[0];
    const float* k     = (const float*)d_in[1];
    const float* v     = (const float*)d_in[2];
    const float* Wq    = (const float*)d_in[3];
    const float* bq    = (const float*)d_in[4];
    const float* Wk    = (const float*)d_in[5];
    const float* bk    = (const float*)d_in[6];
    const float* Wv    = (const float*)d_in[7];
    const float* bv    = (const float*)d_in[8];
    const float* gamma = (const float*)d_in[9];
    const float* beta  = (const float*)d_in[10];
    float* out = (float*)d_out;

    float* Og;
    __half *whi, *wlo, *qhi, *khi, *klo, *vhi, *vlo;
    cudaGetSymbolAddress((void**)&Og, g_O);
    cudaGetSymbolAddress((void**)&whi, g_Wthi);
    cudaGetSymbolAddress((void**)&wlo, g_Wtlo);
    cudaGetSymbolAddress((void**)&qhi, g_Qhi);
    cudaGetSymbolAddress((void**)&khi, g_Khi);
    cudaGetSymbolAddress((void**)&klo, g_Klo);
    cudaGetSymbolAddress((void**)&vhi, g_Vhi);
    cudaGetSymbolAddress((void**)&vlo, g_Vlo);

    cudaFuncSetAttribute(gemm_mma_kernel, cudaFuncAttributeMaxDynamicSharedMemorySize,
                         GEMM_SMEM_BYTES);
    cudaFuncSetAttribute(attn_reg_kernel, cudaFuncAttributeMaxDynamicSharedMemorySize,
                         ATTN_SMEM);

    convert_w_kernel<<<dim3(Dm / 32, Dm / 32, 3), dim3(32, 8)>>>(Wq, Wk, Wv, whi, wlo);

    gemm_mma_kernel<<<dim3(Dm / 128, NROWS / 128, 3), 512, GEMM_SMEM_BYTES>>>(
        q, k, v, whi, wlo, bq, bk, bv, qhi, khi, klo, vhi, vlo);

    attn_reg_kernel<<<dim3(Sseq / 128, Bsz * Hh), 256, ATTN_SMEM>>>(
        qhi, khi, klo, vhi, vlo, Og);

    ln_kernel<<<NROWS, 192>>>(Og, gamma, beta, out);
}

// round 17
// speedup vs baseline: 1.1864x; 1.1009x over previous
#include <cuda_runtime.h>
#include <cuda_fp16.h>
#include <math.h>
#include <stdint.h>

#define Bsz   4
#define Sseq  2048
#define Dm    768
#define Hh    16
#define DHh   48
#define NROWS (Bsz * Sseq)
#define XELEMS ((size_t)NROWS * Dm)
#define WELEMS ((size_t)Dm * Dm)

// softmax scale (1/sqrt(48)) * log2(e): folded into Q projection; exp2 in softmax
#define QSCALE 0.2082351f

// Scratch (__device__ globals per allocation-free rule)
__device__ float g_O[NROWS * Dm];
__device__ __half g_Wthi[3 * WELEMS];   // transposed W [n][k], fp16 hi
__device__ __half g_Wtlo[3 * WELEMS];   // fp16 residual
__device__ __half g_Qhi[XELEMS];        // Q: hi only
__device__ __half g_Khi[XELEMS];        // K: hi only (R17)
__device__ __half g_Vhi[XELEMS];
__device__ __half g_Vlo[XELEMS];

// ============================ PTX helpers ==================================
__device__ __forceinline__ uint32_t smem_u32(const void* p) {
    uint32_t a;
    asm("{ .reg .u64 t; cvta.to.shared.u64 t, %1; cvt.u32.u64 %0, t; }" : "=r"(a) : "l"(p));
    return a;
}
__device__ __forceinline__ float ex2(float x) {
    float y; asm("ex2.approx.ftz.f32 %0, %1;" : "=f"(y) : "f"(x)); return y;
}
#define MMA16816(C, a0, a1, a2, a3, b0, b1)                                   \
    asm volatile("mma.sync.aligned.m16n8k16.row.col.f32.f16.f16.f32 "         \
        "{%0,%1,%2,%3}, {%4,%5,%6,%7}, {%8,%9}, {%0,%1,%2,%3};"               \
        : "+f"((C)[0]), "+f"((C)[1]), "+f"((C)[2]), "+f"((C)[3])              \
        : "r"(a0), "r"(a1), "r"(a2), "r"(a3), "r"(b0), "r"(b1))
#define LDSM_X4(r0, r1, r2, r3, addr)                                         \
    asm volatile("ldmatrix.sync.aligned.m8n8.x4.shared.b16 {%0,%1,%2,%3}, [%4];" \
        : "=r"(r0), "=r"(r1), "=r"(r2), "=r"(r3) : "r"(addr))
#define LDSM_X4T(r0, r1, r2, r3, addr)                                        \
    asm volatile("ldmatrix.sync.aligned.m8n8.x4.trans.shared.b16 {%0,%1,%2,%3}, [%4];" \
        : "=r"(r0), "=r"(r1), "=r"(r2), "=r"(r3) : "r"(addr))
#define CP_ASYNC16(sa, ga)                                                    \
    asm volatile("cp.async.cg.shared.global [%0], [%1], 16;" :: "r"(sa), "l"(ga))
#define CP_COMMIT() asm volatile("cp.async.commit_group;" ::: "memory")
#define CP_WAIT1()  asm volatile("cp.async.wait_group 1;" ::: "memory")
#define CP_WAIT0()  asm volatile("cp.async.wait_group 0;" ::: "memory")

// Pack two floats to fp16x2 (x -> low half, y -> high half)
__device__ __forceinline__ uint32_t pack_h2(float x, float y) {
    uint32_t r;
    asm("cvt.rn.f16x2.f32 %0, %1, %2;" : "=r"(r) : "f"(y), "f"(x));
    return r;
}
// fp16 split: hi = RN(x), lo = RN(x - hi)
__device__ __forceinline__ uint32_t split_h2(float x, float y, uint32_t& lo) {
    uint32_t hi = pack_h2(x, y);
    __half2 h2 = *(__half2*)&hi;
    float xl = x - __low2float(h2);
    float yl = y - __high2float(h2);
    lo = pack_h2(xl, yl);
    return hi;
}

// ============================ W converter ==================================
__global__ __launch_bounds__(256) void convert_w_kernel(
    const float* __restrict__ wq, const float* __restrict__ wk,
    const float* __restrict__ wv,
    __half* __restrict__ hi, __half* __restrict__ lo)
{
    __shared__ float tile[32][33];
    int z = blockIdx.z;
    const float* W = (z == 0) ? wq : (z == 1) ? wk : wv;
    size_t base = (size_t)z * WELEMS;
    int tx = threadIdx.x, ty = threadIdx.y;
    int bx = blockIdx.x, by = blockIdx.y;
#pragma unroll
    for (int i = 0; i < 4; i++) {
        int kk = by * 32 + ty + i * 8;
        int n = bx * 32 + tx;
        tile[ty + i * 8][tx] = W[kk * Dm + n];
    }
    __syncthreads();
#pragma unroll
    for (int i = 0; i < 4; i++) {
        int n = bx * 32 + ty + i * 8;
        int kk = by * 32 + tx;
        float v = tile[tx][ty + i * 8];
        __half h = __float2half_rn(v);
        __half l = __float2half_rn(v - __half2float(h));
        hi[base + n * Dm + kk] = h;
        lo[base + n * Dm + kk] = l;
    }
}

// ================= batched mma.sync GEMM (fp16 split-2) ====================
// Y = (X@W + bias)*scale. A = fp16(X) in-kernel (hi only); B = Whi + Wlo.
// D = Ah*Bh + Ah*Bl. CTA 128x128, BK=64, 512 threads, warp tile 32x32.
#define GBK   64
#define GLDA  72                              // 64 + 8 pad (144 B rows)
#define GPART (128 * GLDA * 2)                // 18432 B per operand array
#define GBUF  (3 * GPART)                     // Ah, Bh, Bl = 55296 B
#define GEMM_SMEM_BYTES (2 * GBUF)            // 110592 B (epilogue 64 KB fits)
#define GNCHK (Dm / GBK)                      // 12

__global__ __launch_bounds__(512) void gemm_mma_kernel(
    const float* __restrict__ xq, const float* __restrict__ xk,
    const float* __restrict__ xv,
    const __half* __restrict__ whi, const __half* __restrict__ wlo,
    const float* __restrict__ bq, const float* __restrict__ bk,
    const float* __restrict__ bv,
    __half* __restrict__ qhi, __half* __restrict__ khi,
    __half* __restrict__ vhi, __half* __restrict__ vlo)
{
    extern __shared__ __align__(128) char smraw[];
    uint32_t smb = smem_u32(smraw);
    int z = blockIdx.z;
    const float* Af = (z == 0) ? xq : (z == 1) ? xk : xv;
    const __half* Bhi = whi + (size_t)z * WELEMS;
    const __half* Blo = wlo + (size_t)z * WELEMS;
    const float* bias = (z == 0) ? bq : (z == 1) ? bk : bv;
    __half* Yhi = (z == 0) ? qhi : (z == 1) ? khi : vhi;
    __half* Ylo = (z == 2) ? vlo : (__half*)0;     // only V keeps a residual
    float scale = (z == 0) ? QSCALE : 1.0f;

    int tid = threadIdx.x;
    int w = tid >> 5, lane = tid & 31;
    int bm = blockIdx.y * 128;
    int bn = blockIdx.x * 128;

    int wm = (w >> 2) * 32;
    int wn = (w & 3) * 32;

    int mat = lane >> 3;
    int arow = ((mat & 1) << 3) + (lane & 7);
    int acol8 = (mat >> 1) << 3;
    int brow = ((mat >> 1) << 3) + (lane & 7);
    int bcol8 = (mat & 1) << 3;

    // A loader: 128 rows x 16 float4/row = 2048 -> 4/thread
    int a_row0 = tid >> 4, a_f4 = (tid & 15);

    float c[2][4][4];
#pragma unroll
    for (int mf = 0; mf < 2; mf++)
#pragma unroll
        for (int nf = 0; nf < 4; nf++)
#pragma unroll
            for (int e = 0; e < 4; e++) c[mf][nf][e] = 0.f;

// B: 2 arrays x 128 rows x 8 segs(16B) = 2048 -> 4/thread
#define B_ISSUE(c0, bufsel) do {                                              \
    int k0_ = (c0) * GBK;                                                     \
    uint32_t bb_ = smb + (bufsel) * GBUF;                                     \
    _Pragma("unroll")                                                         \
    for (int it = 0; it < 4; it++) {                                          \
        int idx = tid + it * 512;                                             \
        int part = idx >> 10;                                                 \
        int rem = idx & 1023;                                                 \
        int row = rem >> 3, seg = rem & 7;                                    \
        const __half* ga = (part ? Blo : Bhi) +                               \
            (size_t)(bn + row) * Dm + k0_ + seg * 8;                          \
        uint32_t sa = bb_ + (1 + part) * GPART + row * (GLDA * 2) + seg * 16; \
        CP_ASYNC16(sa, ga);                                                   \
    }                                                                         \
    CP_COMMIT();                                                              \
} while (0)

#define A_LDG(c0, regs) do {                                                  \
    int k0_ = (c0) * GBK;                                                     \
    _Pragma("unroll")                                                         \
    for (int it = 0; it < 4; it++)                                            \
        (regs)[it] = *(const float4*)(Af +                                    \
            (size_t)(bm + a_row0 + it * 32) * Dm + k0_ + a_f4 * 4);           \
} while (0)

#define A_STS(bufsel, regs) do {                                              \
    _Pragma("unroll")                                                         \
    for (int it = 0; it < 4; it++) {                                          \
        int row = a_row0 + it * 32;                                           \
        float4 v = (regs)[it];                                                \
        uint32_t h01 = pack_h2(v.x, v.y);                                     \
        uint32_t h23 = pack_h2(v.z, v.w);                                     \
        uint32_t off = row * (GLDA * 2) + a_f4 * 8;                           \
        *(uint2*)(smraw + (bufsel) * GBUF + off) = make_uint2(h01, h23);      \
    }                                                                         \
} while (0)

    float4 aregs[4];
    B_ISSUE(0, 0);
    A_LDG(0, aregs);
    A_STS(0, aregs);

    for (int cc = 0; cc < GNCHK; cc++) {
        int buf = cc & 1;
        if (cc + 1 < GNCHK) {
            A_LDG(cc + 1, aregs);
            B_ISSUE(cc + 1, buf ^ 1);
            CP_WAIT1();
        } else {
            CP_WAIT0();
        }
        __syncthreads();

        uint32_t bb = smb + buf * GBUF;
        uint32_t sAh = bb, sBh = bb + GPART, sBl = bb + 2 * GPART;

#pragma unroll
        for (int ks = 0; ks < 4; ks++) {
            uint32_t ah[2][4];
#pragma unroll
            for (int mf = 0; mf < 2; mf++) {
                uint32_t a = ((wm + mf * 16 + arow) * GLDA + ks * 16 + acol8) * 2;
                LDSM_X4(ah[mf][0], ah[mf][1], ah[mf][2], ah[mf][3], sAh + a);
            }
            uint32_t bh[4][2], bl[4][2];
#pragma unroll
            for (int nf2 = 0; nf2 < 2; nf2++) {
                uint32_t a = ((wn + nf2 * 16 + brow) * GLDA + ks * 16 + bcol8) * 2;
                uint32_t r0, r1, r2, r3;
                LDSM_X4(r0, r1, r2, r3, sBh + a);
                bh[nf2 * 2][0] = r0; bh[nf2 * 2][1] = r1;
                bh[nf2 * 2 + 1][0] = r2; bh[nf2 * 2 + 1][1] = r3;
                LDSM_X4(r0, r1, r2, r3, sBl + a);
                bl[nf2 * 2][0] = r0; bl[nf2 * 2][1] = r1;
                bl[nf2 * 2 + 1][0] = r2; bl[nf2 * 2 + 1][1] = r3;
            }
#pragma unroll
            for (int mf = 0; mf < 2; mf++)
#pragma unroll
                for (int nf = 0; nf < 4; nf++) {
                    MMA16816(c[mf][nf], ah[mf][0], ah[mf][1], ah[mf][2], ah[mf][3],
                             bh[nf][0], bh[nf][1]);
                    MMA16816(c[mf][nf], ah[mf][0], ah[mf][1], ah[mf][2], ah[mf][3],
                             bl[nf][0], bl[nf][1]);
                }
        }

        if (cc + 1 < GNCHK) A_STS(buf ^ 1, aregs);
        __syncthreads();
    }

    // Epilogue: stage f32 tile, bias+scale, emit fp16 (hi, and lo for V only)
    float* sOut = (float*)smraw;
    int g = lane >> 2, t4 = lane & 3;
#pragma unroll
    for (int mf = 0; mf < 2; mf++) {
        int m0 = wm + mf * 16 + g;
#pragma unroll
        for (int nf = 0; nf < 4; nf++) {
            int col = wn + nf * 8 + t4 * 2;
            sOut[m0 * 128 + col]       = c[mf][nf][0];
            sOut[m0 * 128 + col + 1]   = c[mf][nf][1];
            sOut[(m0 + 8) * 128 + col]     = c[mf][nf][2];
            sOut[(m0 + 8) * 128 + col + 1] = c[mf][nf][3];
        }
    }
    __syncthreads();

    bool write_lo = (Ylo != (__half*)0);
#pragma unroll
    for (int it = 0; it < 8; it++) {
        int idx = tid + it * 512;
        int row = idx >> 5, c4 = (idx & 31) * 4;
        float4 o = *(float4*)(sOut + row * 128 + c4);
        const float* bp = bias + bn + c4;
        float y0 = (o.x + bp[0]) * scale;
        float y1 = (o.y + bp[1]) * scale;
        float y2 = (o.z + bp[2]) * scale;
        float y3 = (o.w + bp[3]) * scale;
        size_t off = (size_t)(bm + row) * Dm + bn + c4;
        if (write_lo) {
            uint32_t l01, l23;
            uint32_t h01 = split_h2(y0, y1, l01);
            uint32_t h23 = split_h2(y2, y3, l23);
            *(uint2*)(Yhi + off) = make_uint2(h01, h23);
            *(uint2*)(Ylo + off) = make_uint2(l01, l23);
        } else {
            uint32_t h01 = pack_h2(y0, y1);
            uint32_t h23 = pack_h2(y2, y3);
            *(uint2*)(Yhi + off) = make_uint2(h01, h23);
        }
    }
}

// ============ register-resident flash attention =============
// S = Qh*Kh (plain fp16 QK);  O += Ph*Vh + Ph*Vl.  V via ldmatrix.x4.trans.
// One barrier per KV tile (3-deep ring).
#define LDA 56
#define QARR (128 * LDA * 2)
#define KARR (64 * LDA * 2)
#define BUFB (3 * KARR)                 // Kh, Vh, Vl = 21504 B
#define ATTN_SMEM (QARR + 3 * BUFB)     // 14336 + 64512 = 78848

__global__ __launch_bounds__(256, 2) void attn_reg_kernel(
    const __half* __restrict__ Qh_g, const __half* __restrict__ Kh_g,
    const __half* __restrict__ Vh_g, const __half* __restrict__ Vl_g,
    float* __restrict__ Og)
{
    extern __shared__ __align__(128) char smraw[];
    uint32_t smb = smem_u32(smraw);
    __half* Qh = (__half*)smraw;

    int qt = (int)gridDim.x - 1 - (int)blockIdx.x;
    int bh = blockIdx.y;
    int b = bh >> 4, h = bh & 15;
    int tid = threadIdx.x;
    int w = tid >> 5, lane = tid & 31;
    int rowbase = b * Sseq;
    int q0 = qt * 128;
    int hoff = h * DHh;
    int ntiles = 2 * qt + 2;

// KV tile issue: 3 arrays x 64 rows x 6 segs = 1152 transfers
#define KV_ISSUE(k0v, slot) do {                                              \
    uint32_t bb = smb + QARR + (slot) * BUFB;                                 \
    _Pragma("unroll")                                                         \
    for (int it = 0; it < 5; it++) {                                          \
        int s = tid + it * 256;                                               \
        if (s < 1152) {                                                       \
            int arr = s / 384, rem = s - arr * 384;                           \
            int r = rem / 6, c16 = rem - r * 6;                               \
            const __half* src = (arr == 0) ? Kh_g : (arr == 1) ? Vh_g : Vl_g; \
            const __half* ga = src + (size_t)(rowbase + (k0v) + r) * Dm + hoff + c16 * 8; \
            uint32_t sa = bb + arr * KARR + r * (LDA * 2) + c16 * 16;         \
            CP_ASYNC16(sa, ga);                                               \
        }                                                                     \
    }                                                                         \
    CP_COMMIT();                                                              \
} while (0)

    KV_ISSUE(0, 0);

    for (int s = tid; s < 768; s += 256) {
        int r = s / 6, c8 = (s % 6) * 8;
        *(uint4*)(Qh + r * LDA + c8) =
            *(const uint4*)(Qh_g + (size_t)(rowbase + q0 + r) * Dm + hoff + c8);
    }
    __syncthreads();

    int mat = lane >> 3;
    int qrow_loc = ((mat & 1) << 3) + (lane & 7);   // also V x4.trans row map
    int qcol8 = (mat >> 1) << 3;                    // also V x4.trans col-block
    int brow = ((mat >> 1) << 3) + (lane & 7);
    int bcol8 = (mat & 1) << 3;

    uint32_t qh[3][4];
#pragma unroll
    for (int ks = 0; ks < 3; ks++) {
        uint32_t a = smb + ((w * 16 + qrow_loc) * LDA + ks * 16 + qcol8) * 2;
        LDSM_X4(qh[ks][0], qh[ks][1], qh[ks][2], qh[ks][3], a);
    }

    int g = lane >> 2, t4 = lane & 3;

    float m0 = -1e30f, m1 = -1e30f, l0 = 0.f, l1 = 0.f;
    float o[6][4];
#pragma unroll
    for (int on = 0; on < 6; on++)
#pragma unroll
        for (int e = 0; e < 4; e++) o[on][e] = 0.f;

    for (int j = 0; j < ntiles; j++) {
        if (j + 1 < ntiles) {
            KV_ISSUE((j + 1) * 64, (j + 1) % 3);
            CP_WAIT1();
        } else {
            CP_WAIT0();
        }
        __syncthreads();   // sole barrier per tile (ring slot reuse at j+2)

        // Fully-masked warp skip: second diagonal tile, rows entirely above diag
        if (j == 2 * qt + 1 && w < 4) continue;

        uint32_t bufb = smb + QARR + (j % 3) * BUFB;
        uint32_t bufKh = bufb;
        uint32_t bufVh = bufb + KARR, bufVl = bufb + 2 * KARR;

        // ---- S = Qh Kh^T (plain fp16 QK) ----
        float sc[8][4];
#pragma unroll
        for (int jn2 = 0; jn2 < 4; jn2++) {
#pragma unroll
            for (int e = 0; e < 4; e++) { sc[2*jn2][e] = 0.f; sc[2*jn2+1][e] = 0.f; }
#pragma unroll
            for (int ks = 0; ks < 3; ks++) {
                uint32_t a = ((jn2 * 16 + brow) * LDA + ks * 16 + bcol8) * 2;
                uint32_t kh0, kh1, kh2, kh3;
                LDSM_X4(kh0, kh1, kh2, kh3, bufKh + a);
                MMA16816(sc[2*jn2],   qh[ks][0], qh[ks][1], qh[ks][2], qh[ks][3], kh0, kh1);
                MMA16816(sc[2*jn2+1], qh[ks][0], qh[ks][1], qh[ks][2], qh[ks][3], kh2, kh3);
            }
        }

        int k0 = j * 64;
        if (j >= 2 * qt) {
            int qg0 = q0 + w * 16 + g;
#pragma unroll
            for (int jn = 0; jn < 8; jn++) {
                int cix = k0 + jn * 8 + 2 * t4;
                if (qg0 < cix)     sc[jn][0] = -1e30f;
                if (qg0 < cix + 1) sc[jn][1] = -1e30f;
                if (qg0 + 8 < cix)     sc[jn][2] = -1e30f;
                if (qg0 + 8 < cix + 1) sc[jn][3] = -1e30f;
            }
        }

        float mx0 = -1e30f, mx1 = -1e30f;
#pragma unroll
        for (int jn = 0; jn < 8; jn++) {
            mx0 = fmaxf(mx0, fmaxf(sc[jn][0], sc[jn][1]));
            mx1 = fmaxf(mx1, fmaxf(sc[jn][2], sc[jn][3]));
        }
        mx0 = fmaxf(mx0, __shfl_xor_sync(0xffffffffu, mx0, 1));
        mx0 = fmaxf(mx0, __shfl_xor_sync(0xffffffffu, mx0, 2));
        mx1 = fmaxf(mx1, __shfl_xor_sync(0xffffffffu, mx1, 1));
        mx1 = fmaxf(mx1, __shfl_xor_sync(0xffffffffu, mx1, 2));
        float mn0 = fmaxf(m0, mx0), mn1 = fmaxf(m1, mx1);
        float al0 = ex2(m0 - mn0), al1 = ex2(m1 - mn1);
        m0 = mn0; m1 = mn1;
        float ps0 = 0.f, ps1 = 0.f;
#pragma unroll
        for (int jn = 0; jn < 8; jn++) {
            sc[jn][0] = ex2(sc[jn][0] - mn0);
            sc[jn][1] = ex2(sc[jn][1] - mn0);
            sc[jn][2] = ex2(sc[jn][2] - mn1);
            sc[jn][3] = ex2(sc[jn][3] - mn1);
            ps0 += sc[jn][0] + sc[jn][1];
            ps1 += sc[jn][2] + sc[jn][3];
        }
        ps0 += __shfl_xor_sync(0xffffffffu, ps0, 1);
        ps0 += __shfl_xor_sync(0xffffffffu, ps0, 2);
        ps1 += __shfl_xor_sync(0xffffffffu, ps1, 1);
        ps1 += __shfl_xor_sync(0xffffffffu, ps1, 2);
        l0 = l0 * al0 + ps0;
        l1 = l1 * al1 + ps1;

#pragma unroll
        for (int on = 0; on < 6; on++) {
            o[on][0] *= al0; o[on][1] *= al0;
            o[on][2] *= al1; o[on][3] *= al1;
        }
        // ---- O += P Vh + P Vl : V via x4.trans (2 n8-tiles per load) ----
#pragma unroll
        for (int ks = 0; ks < 4; ks++) {
            uint32_t pa[4];
            pa[0] = pack_h2(sc[2*ks][0],   sc[2*ks][1]);
            pa[1] = pack_h2(sc[2*ks][2],   sc[2*ks][3]);
            pa[2] = pack_h2(sc[2*ks+1][0], sc[2*ks+1][1]);
            pa[3] = pack_h2(sc[2*ks+1][2], sc[2*ks+1][3]);
#pragma unroll
            for (int on2 = 0; on2 < 3; on2++) {
                uint32_t va = ((ks * 16 + qrow_loc) * LDA + on2 * 16 + qcol8) * 2;
                uint32_t vh0, vh1, vh2, vh3, vl0, vl1, vl2, vl3;
                LDSM_X4T(vh0, vh1, vh2, vh3, bufVh + va);
                LDSM_X4T(vl0, vl1, vl2, vl3, bufVl + va);
                MMA16816(o[2*on2],   pa[0], pa[1], pa[2], pa[3], vh0, vh1);
                MMA16816(o[2*on2],   pa[0], pa[1], pa[2], pa[3], vl0, vl1);
                MMA16816(o[2*on2+1], pa[0], pa[1], pa[2], pa[3], vh2, vh3);
                MMA16816(o[2*on2+1], pa[0], pa[1], pa[2], pa[3], vl2, vl3);
            }
        }
    }

    float inv0 = 1.f / l0, inv1 = 1.f / l1;
    float* op0 = Og + (size_t)(rowbase + q0 + w * 16 + g) * Dm + hoff + 2 * t4;
    float* op1 = op0 + 8 * Dm;
#pragma unroll
    for (int on = 0; on < 6; on++) {
        float2 r0 = make_float2(o[on][0] * inv0, o[on][1] * inv0);
        float2 r1 = make_float2(o[on][2] * inv1, o[on][3] * inv1);
        *(float2*)(op0 + on * 8) = r0;
        *(float2*)(op1 + on * 8) = r1;
    }
}

// ---------------------------------------------------------------------------
// LayerNorm: 192 threads/row, float4 per thread.
// ---------------------------------------------------------------------------
__global__ __launch_bounds__(192) void ln_kernel(
    const float* __restrict__ X, const float* __restrict__ gamma,
    const float* __restrict__ beta, float* __restrict__ Y)
{
    int row = blockIdx.x;
    int tid = threadIdx.x;
    const float* x = X + (size_t)row * Dm;

    float4 v = *(const float4*)(x + tid * 4);
    float s  = v.x + v.y + v.z + v.w;
    float sq = v.x * v.x + v.y * v.y + v.z * v.z + v.w * v.w;

#pragma unroll
    for (int off = 16; off > 0; off >>= 1) {
        s  += __shfl_xor_sync(0xffffffffu, s, off);
        sq += __shfl_xor_sync(0xffffffffu, sq, off);
    }
    __shared__ float red_s[6], red_q[6];
    int wid = tid >> 5, lid = tid & 31;
    if (lid == 0) { red_s[wid] = s; red_q[wid] = sq; }
    __syncthreads();
    float ts = 0.f, tq = 0.f;
#pragma unroll
    for (int i = 0; i < 6; i++) { ts += red_s[i]; tq += red_q[i]; }
    float mu  = ts * (1.f / Dm);
    float var = tq * (1.f / Dm) - mu * mu;
    float inv = rsqrtf(var + 1e-3f);

    float4 gmv = *(const float4*)(gamma + tid * 4);
    float4 btv = *(const float4*)(beta + tid * 4);
    float4 yv;
    yv.x = (v.x - mu) * inv * gmv.x + btv.x;
    yv.y = (v.y - mu) * inv * gmv.y + btv.y;
    yv.z = (v.z - mu) * inv * gmv.z + btv.z;
    yv.w = (v.w - mu) * inv * gmv.w + btv.w;
    *(float4*)(Y + (size_t)row * Dm + tid * 4) = yv;
}

// ---------------------------------------------------------------------------
extern "C" void kernel_launch(void* const* d_in, const int* in_sizes, int n_in,
                              void* d_out, int out_size)
{
    const float* q     = (const float*)d_in[0];
    const float* k     = (const float*)d_in[1];
    const float* v     = (const float*)d_in[2];
    const float* Wq    = (const float*)d_in[3];
    const float* bq    = (const float*)d_in[4];
    const float* Wk    = (const float*)d_in[5];
    const float* bk    = (const float*)d_in[6];
    const float* Wv    = (const float*)d_in[7];
    const float* bv    = (const float*)d_in[8];
    const float* gamma = (const float*)d_in[9];
    const float* beta  = (const float*)d_in[10];
    float* out = (float*)d_out;

    float* Og;
    __half *whi, *wlo, *qhi, *khi, *vhi, *vlo;
    cudaGetSymbolAddress((void**)&Og, g_O);
    cudaGetSymbolAddress((void**)&whi, g_Wthi);
    cudaGetSymbolAddress((void**)&wlo, g_Wtlo);
    cudaGetSymbolAddress((void**)&qhi, g_Qhi);
    cudaGetSymbolAddress((void**)&khi, g_Khi);
    cudaGetSymbolAddress((void**)&vhi, g_Vhi);
    cudaGetSymbolAddress((void**)&vlo, g_Vlo);

    cudaFuncSetAttribute(gemm_mma_kernel, cudaFuncAttributeMaxDynamicSharedMemorySize,
                         GEMM_SMEM_BYTES);
    cudaFuncSetAttribute(attn_reg_kernel, cudaFuncAttributeMaxDynamicSharedMemorySize,
                         ATTN_SMEM);

    convert_w_kernel<<<dim3(Dm / 32, Dm / 32, 3), dim3(32, 8)>>>(Wq, Wk, Wv, whi, wlo);

    gemm_mma_kernel<<<dim3(Dm / 128, NROWS / 128, 3), 512, GEMM_SMEM_BYTES>>>(
        q, k, v, whi, wlo, bq, bk, bv, qhi, khi, vhi, vlo);

    attn_reg_kernel<<<dim3(Sseq / 128, Bsz * Hh), 256, ATTN_SMEM>>>(
        qhi, khi, vhi, vlo, Og);

    ln_kernel<<<NROWS, 192>>>(Og, gamma, beta, out);
}